// round 9
// baseline (speedup 1.0000x reference)
#include <cuda_runtime.h>
#include <math.h>

// Problem constants
#define BSZ  2
#define LSEQ 2048
#define EMB  1024
#define HN   16
#define DHD  64
#define DFF  4096
#define MR   (BSZ*LSEQ)     // 4096 rows
#define N3E  (3*EMB)        // 3072

// ---------------------------------------------------------------------------
// Scratch (device globals; no allocation in kernel_launch)
// ---------------------------------------------------------------------------
__device__ float g_wqkv[(size_t)EMB * N3E];       // packed QKV weights (E x 3072)
__device__ float g_bqkv[N3E];                     // packed QKV bias
__device__ float g_qkv[(size_t)MR * N3E];         // q|k|v, row = token, col = proj*1024+h*64+d
__device__ float g_z  [(size_t)MR * EMB];         // attention output (concat heads)
__device__ float g_t1 [(size_t)MR * EMB];         // pre-LN residual buffer (reused)
__device__ float g_h  [(size_t)MR * EMB];         // post-LN1 hidden
__device__ float g_ff [(size_t)MR * DFF];         // FFN intermediate

// ---------------------------------------------------------------------------
// Pack Wq/Wk/Wv (H,E,Dh) -> Wqkv (E, 3*E) row-major; biases (H,Dh) -> (3*E)
// ---------------------------------------------------------------------------
__global__ void pack_qkv_kernel(const float* __restrict__ Wq, const float* __restrict__ Wk,
                                const float* __restrict__ Wv, const float* __restrict__ bq,
                                const float* __restrict__ bk, const float* __restrict__ bv)
{
    int idx = blockIdx.x * blockDim.x + threadIdx.x;
    const int total = EMB * N3E;
    if (idx < total) {
        int n = idx % N3E;
        int e = idx / N3E;
        int proj = n / EMB;
        int hd   = n % EMB;              // h*64 + d
        const float* W = (proj == 0) ? Wq : (proj == 1) ? Wk : Wv;
        // W[h][e][d] at h*E*Dh + e*Dh + d
        g_wqkv[idx] = W[(size_t)(hd >> 6) * EMB * DHD + (size_t)e * DHD + (hd & 63)];
    }
    if (idx < N3E) {
        int proj = idx / EMB;
        int hd   = idx % EMB;
        const float* bb = (proj == 0) ? bq : (proj == 1) ? bk : bv;
        g_bqkv[idx] = bb[hd];
    }
}

// ---------------------------------------------------------------------------
// SGEMM: C(MxN) = A(MxK) @ B(KxN) + bias[n] (+ res[m][n]) (relu optional)
// 128x128 tile, BK=8, 256 threads, 8x8 per thread, double-buffered smem.
// M,N multiples of 128; K multiple of 8.
// ---------------------------------------------------------------------------
template<bool RELU, bool ADDRES>
__global__ __launch_bounds__(256, 2)
void sgemm128(const float* __restrict__ A, const float* __restrict__ B,
              const float* __restrict__ bias, const float* __restrict__ res,
              float* __restrict__ C, int M, int N, int K)
{
    __shared__ float As[2][8][128];
    __shared__ float Bs[2][8][128];

    const int tid = threadIdx.x;
    const int bx = blockIdx.x, by = blockIdx.y;

    // global load indices
    const int arow = tid >> 1;             // 0..127
    const int acol = (tid & 1) << 2;       // 0 or 4
    const int brow = tid >> 5;             // 0..7
    const int bcol = (tid & 31) << 2;      // 0..124

    const float* Ag = A + (size_t)(by * 128 + arow) * K + acol;
    const float* Bg = B + (size_t)brow * N + bx * 128 + bcol;

    // prologue: load tile 0
    {
        float4 av = *(const float4*)Ag;
        As[0][acol + 0][arow] = av.x;
        As[0][acol + 1][arow] = av.y;
        As[0][acol + 2][arow] = av.z;
        As[0][acol + 3][arow] = av.w;
        float4 bv = *(const float4*)Bg;
        *(float4*)&Bs[0][brow][bcol] = bv;
    }
    __syncthreads();

    float acc[8][8];
#pragma unroll
    for (int i = 0; i < 8; ++i)
#pragma unroll
        for (int j = 0; j < 8; ++j) acc[i][j] = 0.f;

    const int tx = tid & 15;   // col group
    const int ty = tid >> 4;   // row group
    int buf = 0;

    for (int kt = 0; kt < K; kt += 8) {
        float4 av, bv;
        const bool more = (kt + 8) < K;
        if (more) {
            av = *(const float4*)(Ag + (kt + 8));
            bv = *(const float4*)(Bg + (size_t)(kt + 8) * N);
        }

        const float (*Asb)[128] = As[buf];
        const float (*Bsb)[128] = Bs[buf];
#pragma unroll
        for (int k = 0; k < 8; ++k) {
            float4 a0 = *(const float4*)&Asb[k][ty * 4];
            float4 a1 = *(const float4*)&Asb[k][64 + ty * 4];
            float4 b0 = *(const float4*)&Bsb[k][tx * 4];
            float4 b1 = *(const float4*)&Bsb[k][64 + tx * 4];
            float af[8] = {a0.x, a0.y, a0.z, a0.w, a1.x, a1.y, a1.z, a1.w};
            float bf[8] = {b0.x, b0.y, b0.z, b0.w, b1.x, b1.y, b1.z, b1.w};
#pragma unroll
            for (int i = 0; i < 8; ++i)
#pragma unroll
                for (int j = 0; j < 8; ++j) acc[i][j] += af[i] * bf[j];
        }

        if (more) {
            int nb = buf ^ 1;
            As[nb][acol + 0][arow] = av.x;
            As[nb][acol + 1][arow] = av.y;
            As[nb][acol + 2][arow] = av.z;
            As[nb][acol + 3][arow] = av.w;
            *(float4*)&Bs[nb][brow][bcol] = bv;
            __syncthreads();
            buf = nb;
        }
    }

    // epilogue
#pragma unroll
    for (int i = 0; i < 8; ++i) {
        int m = by * 128 + ((i < 4) ? (ty * 4 + i) : (64 + ty * 4 + i - 4));
#pragma unroll
        for (int jg = 0; jg < 2; ++jg) {
            int n = bx * 128 + jg * 64 + tx * 4;
            float4 v = make_float4(acc[i][jg * 4 + 0], acc[i][jg * 4 + 1],
                                   acc[i][jg * 4 + 2], acc[i][jg * 4 + 3]);
            float4 bi = *(const float4*)&bias[n];
            v.x += bi.x; v.y += bi.y; v.z += bi.z; v.w += bi.w;
            if (ADDRES) {
                float4 r = *(const float4*)&res[(size_t)m * N + n];
                v.x += r.x; v.y += r.y; v.z += r.z; v.w += r.w;
            }
            if (RELU) {
                v.x = fmaxf(v.x, 0.f); v.y = fmaxf(v.y, 0.f);
                v.z = fmaxf(v.z, 0.f); v.w = fmaxf(v.w, 0.f);
            }
            *(float4*)&C[(size_t)m * N + n] = v;
        }
    }
}

// ---------------------------------------------------------------------------
// LayerNorm: one block per row of 1024, eps=1e-5, out = (x-m)/sqrt(v+eps)*g + b
// ---------------------------------------------------------------------------
__device__ __forceinline__ float block_sum_1024(float v, float* red)
{
#pragma unroll
    for (int o = 16; o; o >>= 1) v += __shfl_xor_sync(0xffffffffu, v, o);
    int w = threadIdx.x >> 5;
    if ((threadIdx.x & 31) == 0) red[w] = v;
    __syncthreads();
    if (threadIdx.x < 32) {
        float t = (threadIdx.x < 8) ? red[threadIdx.x] : 0.f;
#pragma unroll
        for (int o = 4; o; o >>= 1) t += __shfl_xor_sync(0xffffffffu, t, o);
        if (threadIdx.x == 0) red[0] = t;
    }
    __syncthreads();
    float r = red[0];
    __syncthreads();
    return r;
}

__global__ __launch_bounds__(256)
void layernorm_kernel(const float* __restrict__ in, const float* __restrict__ g,
                      const float* __restrict__ beta, float* __restrict__ out)
{
    __shared__ float red[8];
    const int row = blockIdx.x;
    const int tid = threadIdx.x;
    float4 v = ((const float4*)(in + (size_t)row * EMB))[tid];
    float s = v.x + v.y + v.z + v.w;
    float mean = block_sum_1024(s, red) * (1.f / EMB);
    float dx = v.x - mean, dy = v.y - mean, dz = v.z - mean, dw = v.w - mean;
    float sq = dx * dx + dy * dy + dz * dz + dw * dw;
    float var = block_sum_1024(sq, red) * (1.f / EMB);
    float rstd = rsqrtf(var + 1e-5f);
    float4 gv = ((const float4*)g)[tid];
    float4 bv = ((const float4*)beta)[tid];
    float4 o;
    o.x = dx * rstd * gv.x + bv.x;
    o.y = dy * rstd * gv.y + bv.y;
    o.z = dz * rstd * gv.z + bv.z;
    o.w = dw * rstd * gv.w + bv.w;
    ((float4*)(out + (size_t)row * EMB))[tid] = o;
}

// ---------------------------------------------------------------------------
// Causal flash attention, fp32. One CTA per (qblock of 64, head, batch).
// qkv layout: row (b*L + l), cols [0,1024)=q, [1024,2048)=k, [2048,3072)=v,
// within each: h*64 + d. z out: row (b*L+l), col h*64 + d (concat-heads).
// ---------------------------------------------------------------------------
struct AttnSmem {
    float Qs[64][68];
    float Ks[64][68];
    float Vs[64][68];
    float Ss[64][68];
    float Pt[64][68];   // transposed probabilities: Pt[j][i]
    float mrow[64];
    float lrow[64];
    float arow[64];
};

#define DOT4(a, b) ((a).x*(b).x + (a).y*(b).y + (a).z*(b).z + (a).w*(b).w)

__global__ __launch_bounds__(256, 1)
void attn_kernel(const float* __restrict__ qkv, float* __restrict__ z)
{
    extern __shared__ char smem_raw[];
    AttnSmem& sm = *reinterpret_cast<AttnSmem*>(smem_raw);

    const int qb = blockIdx.x;        // 0..31
    const int h  = blockIdx.y;        // 0..15
    const int b  = blockIdx.z;        // 0..1
    const int tid = threadIdx.x;      // 256
    const int tx = tid & 15, ty = tid >> 4;
    const size_t rs = N3E;
    const float scale = 0.125f;       // 1/sqrt(64)

    // load Q tile (pre-scaled)
    const float* qbase = qkv + (size_t)(b * LSEQ + qb * 64) * rs + h * 64;
#pragma unroll
    for (int it = 0; it < 4; ++it) {
        int idx = tid + it * 256;              // 0..1023
        int r = idx >> 4, c4 = (idx & 15) << 2;
        float4 v = *(const float4*)(qbase + (size_t)r * rs + c4);
        sm.Qs[r][c4 + 0] = v.x * scale;
        sm.Qs[r][c4 + 1] = v.y * scale;
        sm.Qs[r][c4 + 2] = v.z * scale;
        sm.Qs[r][c4 + 3] = v.w * scale;
    }
    if (tid < 64) { sm.mrow[tid] = -1e30f; sm.lrow[tid] = 0.f; }

    float acc[4][4];
#pragma unroll
    for (int i = 0; i < 4; ++i)
#pragma unroll
        for (int j = 0; j < 4; ++j) acc[i][j] = 0.f;

    for (int kb = 0; kb <= qb; ++kb) {
        __syncthreads();  // previous PV done reading Pt/Vs; Q stores visible on first iter

        const float* kbase = qkv + (size_t)(b * LSEQ + kb * 64) * rs + EMB + h * 64;
        const float* vbase = kbase + EMB;
#pragma unroll
        for (int it = 0; it < 4; ++it) {
            int idx = tid + it * 256;
            int r = idx >> 4, c4 = (idx & 15) << 2;
            float4 kv = *(const float4*)(kbase + (size_t)r * rs + c4);
            sm.Ks[r][c4 + 0] = kv.x; sm.Ks[r][c4 + 1] = kv.y;
            sm.Ks[r][c4 + 2] = kv.z; sm.Ks[r][c4 + 3] = kv.w;
            float4 vv = *(const float4*)(vbase + (size_t)r * rs + c4);
            sm.Vs[r][c4 + 0] = vv.x; sm.Vs[r][c4 + 1] = vv.y;
            sm.Vs[r][c4 + 2] = vv.z; sm.Vs[r][c4 + 3] = vv.w;
        }
        __syncthreads();

        // S = (Q*scale) @ K^T  (rows i = ty+16*ii, cols j = tx+16*jj)
        float s[4][4];
#pragma unroll
        for (int i = 0; i < 4; ++i)
#pragma unroll
            for (int j = 0; j < 4; ++j) s[i][j] = 0.f;
#pragma unroll
        for (int d4 = 0; d4 < 64; d4 += 4) {
            float4 q0 = *(const float4*)&sm.Qs[ty     ][d4];
            float4 q1 = *(const float4*)&sm.Qs[ty + 16][d4];
            float4 q2 = *(const float4*)&sm.Qs[ty + 32][d4];
            float4 q3 = *(const float4*)&sm.Qs[ty + 48][d4];
            float4 k0 = *(const float4*)&sm.Ks[tx     ][d4];
            float4 k1 = *(const float4*)&sm.Ks[tx + 16][d4];
            float4 k2 = *(const float4*)&sm.Ks[tx + 32][d4];
            float4 k3 = *(const float4*)&sm.Ks[tx + 48][d4];
            s[0][0] += DOT4(q0,k0); s[0][1] += DOT4(q0,k1); s[0][2] += DOT4(q0,k2); s[0][3] += DOT4(q0,k3);
            s[1][0] += DOT4(q1,k0); s[1][1] += DOT4(q1,k1); s[1][2] += DOT4(q1,k2); s[1][3] += DOT4(q1,k3);
            s[2][0] += DOT4(q2,k0); s[2][1] += DOT4(q2,k1); s[2][2] += DOT4(q2,k2); s[2][3] += DOT4(q2,k3);
            s[3][0] += DOT4(q3,k0); s[3][1] += DOT4(q3,k1); s[3][2] += DOT4(q3,k2); s[3][3] += DOT4(q3,k3);
        }
#pragma unroll
        for (int ii = 0; ii < 4; ++ii)
#pragma unroll
            for (int jj = 0; jj < 4; ++jj)
                sm.Ss[ty + 16 * ii][tx + 16 * jj] = s[ii][jj];
        __syncthreads();

        // online softmax per row (threads 0..63)
        if (tid < 64) {
            const int r = tid;
            const bool diag = (kb == qb);
            float m_old = sm.mrow[r];
            float mmax = m_old;
#pragma unroll
            for (int j4 = 0; j4 < 64; j4 += 4) {
                float4 v = *(const float4*)&sm.Ss[r][j4];
                if (diag) {
                    if (j4 + 0 > r) v.x = -1e30f;
                    if (j4 + 1 > r) v.y = -1e30f;
                    if (j4 + 2 > r) v.z = -1e30f;
                    if (j4 + 3 > r) v.w = -1e30f;
                }
                mmax = fmaxf(mmax, fmaxf(fmaxf(v.x, v.y), fmaxf(v.z, v.w)));
            }
            float alpha = expf(m_old - mmax);
            float lsum = 0.f;
#pragma unroll
            for (int j4 = 0; j4 < 64; j4 += 4) {
                float4 v = *(const float4*)&sm.Ss[r][j4];
                float p0 = (diag && (j4 + 0 > r)) ? 0.f : expf(v.x - mmax);
                float p1 = (diag && (j4 + 1 > r)) ? 0.f : expf(v.y - mmax);
                float p2 = (diag && (j4 + 2 > r)) ? 0.f : expf(v.z - mmax);
                float p3 = (diag && (j4 + 3 > r)) ? 0.f : expf(v.w - mmax);
                sm.Pt[j4 + 0][r] = p0;
                sm.Pt[j4 + 1][r] = p1;
                sm.Pt[j4 + 2][r] = p2;
                sm.Pt[j4 + 3][r] = p3;
                lsum += p0 + p1 + p2 + p3;
            }
            sm.mrow[r] = mmax;
            sm.lrow[r] = sm.lrow[r] * alpha + lsum;
            sm.arow[r] = alpha;
        }
        __syncthreads();

        // O = O*alpha + P @ V
        float a0 = sm.arow[ty], a1 = sm.arow[ty + 16];
        float a2 = sm.arow[ty + 32], a3 = sm.arow[ty + 48];
#pragma unroll
        for (int jj = 0; jj < 4; ++jj) {
            acc[0][jj] *= a0; acc[1][jj] *= a1;
            acc[2][jj] *= a2; acc[3][jj] *= a3;
        }
#pragma unroll 16
        for (int k = 0; k < 64; ++k) {
            float p0 = sm.Pt[k][ty],      p1 = sm.Pt[k][ty + 16];
            float p2 = sm.Pt[k][ty + 32], p3 = sm.Pt[k][ty + 48];
            float v0 = sm.Vs[k][tx],      v1 = sm.Vs[k][tx + 16];
            float v2 = sm.Vs[k][tx + 32], v3 = sm.Vs[k][tx + 48];
            acc[0][0] += p0 * v0; acc[0][1] += p0 * v1; acc[0][2] += p0 * v2; acc[0][3] += p0 * v3;
            acc[1][0] += p1 * v0; acc[1][1] += p1 * v1; acc[1][2] += p1 * v2; acc[1][3] += p1 * v3;
            acc[2][0] += p2 * v0; acc[2][1] += p2 * v1; acc[2][2] += p2 * v2; acc[2][3] += p2 * v3;
            acc[3][0] += p3 * v0; acc[3][1] += p3 * v1; acc[3][2] += p3 * v2; acc[3][3] += p3 * v3;
        }
    }

    // final normalize + store
    float inv[4];
    inv[0] = 1.f / sm.lrow[ty];      inv[1] = 1.f / sm.lrow[ty + 16];
    inv[2] = 1.f / sm.lrow[ty + 32]; inv[3] = 1.f / sm.lrow[ty + 48];
    float* zb = z + (size_t)(b * LSEQ + qb * 64) * EMB + h * 64;
#pragma unroll
    for (int ii = 0; ii < 4; ++ii) {
        int i = ty + 16 * ii;
#pragma unroll
        for (int jj = 0; jj < 4; ++jj)
            zb[(size_t)i * EMB + tx + 16 * jj] = acc[ii][jj] * inv[ii];
    }
}

// ---------------------------------------------------------------------------
// Launch
// ---------------------------------------------------------------------------
extern "C" void kernel_launch(void* const* d_in, const int* in_sizes, int n_in,
                              void* d_out, int out_size)
{
    const float* x    = (const float*)d_in[0];
    // d_in[1] = mask (causal tril) — handled analytically, unused
    const float* Wq   = (const float*)d_in[2];
    const float* bq   = (const float*)d_in[3];
    const float* Wk   = (const float*)d_in[4];
    const float* bk   = (const float*)d_in[5];
    const float* Wv   = (const float*)d_in[6];
    const float* bv   = (const float*)d_in[7];
    const float* Wo   = (const float*)d_in[8];
    const float* bo   = (const float*)d_in[9];
    const float* W1   = (const float*)d_in[10];
    const float* c1   = (const float*)d_in[11];
    const float* W2   = (const float*)d_in[12];
    const float* c2   = (const float*)d_in[13];
    const float* g1   = (const float*)d_in[14];
    const float* be1  = (const float*)d_in[15];
    const float* g2   = (const float*)d_in[16];
    const float* be2  = (const float*)d_in[17];
    float* out = (float*)d_out;

    float *wqkv, *bqkv, *qkv, *zz, *t1, *hh, *ff;
    cudaGetSymbolAddress((void**)&wqkv, g_wqkv);
    cudaGetSymbolAddress((void**)&bqkv, g_bqkv);
    cudaGetSymbolAddress((void**)&qkv,  g_qkv);
    cudaGetSymbolAddress((void**)&zz,   g_z);
    cudaGetSymbolAddress((void**)&t1,   g_t1);
    cudaGetSymbolAddress((void**)&hh,   g_h);
    cudaGetSymbolAddress((void**)&ff,   g_ff);

    cudaFuncSetAttribute(attn_kernel, cudaFuncAttributeMaxDynamicSharedMemorySize,
                         (int)sizeof(AttnSmem));

    // 1. pack QKV weights/biases
    pack_qkv_kernel<<<(EMB * N3E + 255) / 256, 256>>>(Wq, Wk, Wv, bq, bk, bv);

    // 2. QKV projection: qkv = x @ Wqkv + bqkv   (4096 x 3072, K=1024)
    sgemm128<false, false><<<dim3(N3E / 128, MR / 128), 256>>>(
        x, wqkv, bqkv, nullptr, qkv, MR, N3E, EMB);

    // 3. causal attention -> z
    attn_kernel<<<dim3(LSEQ / 64, HN, BSZ), 256, sizeof(AttnSmem)>>>(qkv, zz);

    // 4. t1 = z @ Wo + bo + x
    sgemm128<false, true><<<dim3(EMB / 128, MR / 128), 256>>>(
        zz, Wo, bo, x, t1, MR, EMB, EMB);

    // 5. h = LN1(t1)
    layernorm_kernel<<<MR, 256>>>(t1, g1, be1, hh);

    // 6. ff = relu(h @ W1 + c1)   (4096 x 4096, K=1024)
    sgemm128<true, false><<<dim3(DFF / 128, MR / 128), 256>>>(
        hh, W1, c1, nullptr, ff, MR, DFF, EMB);

    // 7. t1 = ff @ W2 + c2 + h   (4096 x 1024, K=4096)
    sgemm128<false, true><<<dim3(EMB / 128, MR / 128), 256>>>(
        ff, W2, c2, hh, t1, MR, EMB, DFF);

    // 8. out = LN2(t1)
    layernorm_kernel<<<MR, 256>>>(t1, g2, be2, out);
}

// round 11
// speedup vs baseline: 1.2100x; 1.2100x over previous
#include <cuda_runtime.h>
#include <cuda_bf16.h>
#include <mma.h>
#include <math.h>
#include <stdint.h>

using namespace nvcuda;

// Problem constants
#define BSZ  2
#define LSEQ 2048
#define EMB  1024
#define HN   16
#define DHD  64
#define DFF  4096
#define MR   (BSZ*LSEQ)     // 4096 rows
#define N3E  (3*EMB)        // 3072

// ---------------------------------------------------------------------------
// Scratch (device globals; no allocation in kernel_launch)
// ---------------------------------------------------------------------------
__device__ float g_wqkv[(size_t)EMB * N3E];       // packed QKV weights (E x 3072)
__device__ float g_bqkv[N3E];                     // packed QKV bias
__device__ float g_qkv[(size_t)MR * N3E];         // q|k|v
__device__ float g_z  [(size_t)MR * EMB];         // attention output
__device__ float g_t1 [(size_t)MR * EMB];         // pre-LN residual buffer
__device__ float g_h  [(size_t)MR * EMB];         // post-LN1 hidden
__device__ float g_ff [(size_t)MR * DFF];         // FFN intermediate

// ---------------------------------------------------------------------------
// Pack Wq/Wk/Wv (H,E,Dh) -> Wqkv (E, 3*E) row-major; biases -> (3*E)
// ---------------------------------------------------------------------------
__global__ void pack_qkv_kernel(const float* __restrict__ Wq, const float* __restrict__ Wk,
                                const float* __restrict__ Wv, const float* __restrict__ bq,
                                const float* __restrict__ bk, const float* __restrict__ bv)
{
    int idx = blockIdx.x * blockDim.x + threadIdx.x;
    const int total = EMB * N3E;
    if (idx < total) {
        int n = idx % N3E;
        int e = idx / N3E;
        int proj = n / EMB;
        int hd   = n % EMB;
        const float* W = (proj == 0) ? Wq : (proj == 1) ? Wk : Wv;
        g_wqkv[idx] = W[(size_t)(hd >> 6) * EMB * DHD + (size_t)e * DHD + (hd & 63)];
    }
    if (idx < N3E) {
        int proj = idx / EMB;
        int hd   = idx % EMB;
        const float* bb = (proj == 0) ? bq : (proj == 1) ? bk : bv;
        g_bqkv[idx] = bb[hd];
    }
}

// ---------------------------------------------------------------------------
// bf16 split helpers
// ---------------------------------------------------------------------------
__device__ __forceinline__ void split2(float v, __nv_bfloat16& h, __nv_bfloat16& l) {
    h = __float2bfloat16(v);
    l = __float2bfloat16(v - __bfloat162float(h));
}

__device__ __forceinline__ void store_split4(__nv_bfloat16* h, __nv_bfloat16* l, float4 v) {
    __nv_bfloat162 h01, h23, l01, l23;
    split2(v.x, h01.x, l01.x);
    split2(v.y, h01.y, l01.y);
    split2(v.z, h23.x, l23.x);
    split2(v.w, h23.y, l23.y);
    *(__nv_bfloat162*)(h + 0) = h01;
    *(__nv_bfloat162*)(h + 2) = h23;
    *(__nv_bfloat162*)(l + 0) = l01;
    *(__nv_bfloat162*)(l + 2) = l23;
}

// ---------------------------------------------------------------------------
// WMMA bf16x3 GEMM: C(MxN) = A(MxK) @ B(KxN) + bias[n] (+ res) (relu optional)
// CTA tile 128x128, BK=32, 8 warps (2x4), warp tile 64x32 (4x2 wmma frags).
// fp32 operands split to bf16 hi/lo in smem; D += ah*bh + ah*bl + al*bh.
// Dynamic smem layout (bf16 elems):
//   AH [2][128][40] at 0      (10240)
//   AL [2][128][40] at 10240  (10240)
//   BH [2][32][136] at 20480  (8704)
//   BL [2][32][136] at 29184  (8704)
// total 37888 elems = 75776 bytes.
// ---------------------------------------------------------------------------
#define BK        32
#define A_STRIDE  40
#define B_STRIDE  136
#define A_BUFSZ   (128 * A_STRIDE)      // 5120
#define B_BUFSZ   (32 * B_STRIDE)       // 4352
#define AL_OFF    (2 * A_BUFSZ)         // 10240
#define BH_OFF    (2 * AL_OFF)          // 20480
#define BL_OFF    (BH_OFF + 2 * B_BUFSZ) // 29184
#define GEMM_SMEM ((BL_OFF + 2 * B_BUFSZ) * 2)   // 75776 bytes

template<bool RELU, bool ADDRES>
__global__ __launch_bounds__(256)
void bgemm(const float* __restrict__ A, const float* __restrict__ B,
           const float* __restrict__ bias, const float* __restrict__ res,
           float* __restrict__ C, int M, int N, int K)
{
    extern __shared__ __nv_bfloat16 sm[];
    __nv_bfloat16* AH = sm;
    __nv_bfloat16* AL = sm + AL_OFF;
    __nv_bfloat16* BH = sm + BH_OFF;
    __nv_bfloat16* BL = sm + BL_OFF;

    const int tid = threadIdx.x;
    const int bx = blockIdx.x, by = blockIdx.y;
    const int wid = tid >> 5;
    const int wm = wid >> 2;          // 0..1  (row group of 64)
    const int wn = wid & 3;           // 0..3  (col group of 32)

    // global load indices: A 128x32 (4 float4/thread), B 32x128 (4 float4/thread)
    const int arow = tid >> 3;              // 0..31, rows arow + i*32
    const int acol = (tid & 7) << 2;        // 0..28
    const int brow = tid >> 5;              // 0..7,  rows brow + i*8
    const int bcol = (tid & 31) << 2;       // 0..124

    const float* Ag = A + (size_t)(by * 128 + arow) * K + acol;
    const float* Bg = B + (size_t)brow * N + bx * 128 + bcol;

    wmma::fragment<wmma::accumulator, 16, 16, 16, float> acc[4][2];
#pragma unroll
    for (int i = 0; i < 4; ++i)
#pragma unroll
        for (int j = 0; j < 2; ++j) wmma::fill_fragment(acc[i][j], 0.f);

    // prologue: tile 0 -> buf 0
#pragma unroll
    for (int i = 0; i < 4; ++i) {
        float4 v = *(const float4*)(Ag + (size_t)(i * 32) * K);
        int r = arow + i * 32;
        store_split4(&AH[r * A_STRIDE + acol], &AL[r * A_STRIDE + acol], v);
    }
#pragma unroll
    for (int i = 0; i < 4; ++i) {
        float4 v = *(const float4*)(Bg + (size_t)(i * 8) * N);
        int r = brow + i * 8;
        store_split4(&BH[r * B_STRIDE + bcol], &BL[r * B_STRIDE + bcol], v);
    }
    __syncthreads();

    int buf = 0;
    for (int kt = 0; kt < K; kt += BK) {
        float4 av[4], bv[4];
        const bool more = (kt + BK) < K;
        if (more) {
#pragma unroll
            for (int i = 0; i < 4; ++i)
                av[i] = *(const float4*)(Ag + (kt + BK) + (size_t)(i * 32) * K);
#pragma unroll
            for (int i = 0; i < 4; ++i)
                bv[i] = *(const float4*)(Bg + (size_t)(kt + BK + i * 8) * N);
        }

        const __nv_bfloat16* ah_base = AH + buf * A_BUFSZ;
        const __nv_bfloat16* al_base = AL + buf * A_BUFSZ;
        const __nv_bfloat16* bh_base = BH + buf * B_BUFSZ;
        const __nv_bfloat16* bl_base = BL + buf * B_BUFSZ;

#pragma unroll
        for (int ks = 0; ks < 2; ++ks) {
            wmma::fragment<wmma::matrix_a, 16, 16, 16, __nv_bfloat16, wmma::row_major> fah[4], fal[4];
            wmma::fragment<wmma::matrix_b, 16, 16, 16, __nv_bfloat16, wmma::row_major> fbh[2], fbl[2];
#pragma unroll
            for (int i = 0; i < 4; ++i) {
                int off = (wm * 64 + i * 16) * A_STRIDE + ks * 16;
                wmma::load_matrix_sync(fah[i], ah_base + off, A_STRIDE);
                wmma::load_matrix_sync(fal[i], al_base + off, A_STRIDE);
            }
#pragma unroll
            for (int j = 0; j < 2; ++j) {
                int off = (ks * 16) * B_STRIDE + wn * 32 + j * 16;
                wmma::load_matrix_sync(fbh[j], bh_base + off, B_STRIDE);
                wmma::load_matrix_sync(fbl[j], bl_base + off, B_STRIDE);
            }
#pragma unroll
            for (int i = 0; i < 4; ++i)
#pragma unroll
                for (int j = 0; j < 2; ++j) {
                    wmma::mma_sync(acc[i][j], fah[i], fbh[j], acc[i][j]);
                    wmma::mma_sync(acc[i][j], fah[i], fbl[j], acc[i][j]);
                    wmma::mma_sync(acc[i][j], fal[i], fbh[j], acc[i][j]);
                }
        }

        if (more) {
            int nb = buf ^ 1;
#pragma unroll
            for (int i = 0; i < 4; ++i) {
                int r = arow + i * 32;
                store_split4(&AH[nb * A_BUFSZ + r * A_STRIDE + acol],
                             &AL[nb * A_BUFSZ + r * A_STRIDE + acol], av[i]);
            }
#pragma unroll
            for (int i = 0; i < 4; ++i) {
                int r = brow + i * 8;
                store_split4(&BH[nb * B_BUFSZ + r * B_STRIDE + bcol],
                             &BL[nb * B_BUFSZ + r * B_STRIDE + bcol], bv[i]);
            }
            __syncthreads();
            buf = nb;
        }
    }

    // store raw accumulators to C
#pragma unroll
    for (int i = 0; i < 4; ++i)
#pragma unroll
        for (int j = 0; j < 2; ++j) {
            float* cp = C + (size_t)(by * 128 + wm * 64 + i * 16) * N
                          + bx * 128 + wn * 32 + j * 16;
            wmma::store_matrix_sync(cp, acc[i][j], N, wmma::mem_row_major);
        }
    __syncthreads();   // block-scope visibility of global stores

    // fused epilogue: bias (+res) (+relu), RMW over the CTA's tile
    {
        const int r = tid >> 1;
        const int cb = (tid & 1) * 64;
        float* Crow = C + (size_t)(by * 128 + r) * N + bx * 128 + cb;
        const float* bp = bias + bx * 128 + cb;
        const float* rp = ADDRES ? (res + (size_t)(by * 128 + r) * N + bx * 128 + cb) : nullptr;
#pragma unroll
        for (int g = 0; g < 16; ++g) {
            float4 v = *(float4*)(Crow + g * 4);
            float4 bi = *(const float4*)(bp + g * 4);
            v.x += bi.x; v.y += bi.y; v.z += bi.z; v.w += bi.w;
            if (ADDRES) {
                float4 rr = *(const float4*)(rp + g * 4);
                v.x += rr.x; v.y += rr.y; v.z += rr.z; v.w += rr.w;
            }
            if (RELU) {
                v.x = fmaxf(v.x, 0.f); v.y = fmaxf(v.y, 0.f);
                v.z = fmaxf(v.z, 0.f); v.w = fmaxf(v.w, 0.f);
            }
            *(float4*)(Crow + g * 4) = v;
        }
    }
}

// ---------------------------------------------------------------------------
// LayerNorm: one block per row of 1024
// ---------------------------------------------------------------------------
__device__ __forceinline__ float block_sum_1024(float v, float* red)
{
#pragma unroll
    for (int o = 16; o; o >>= 1) v += __shfl_xor_sync(0xffffffffu, v, o);
    int w = threadIdx.x >> 5;
    if ((threadIdx.x & 31) == 0) red[w] = v;
    __syncthreads();
    if (threadIdx.x < 32) {
        float t = (threadIdx.x < 8) ? red[threadIdx.x] : 0.f;
#pragma unroll
        for (int o = 4; o; o >>= 1) t += __shfl_xor_sync(0xffffffffu, t, o);
        if (threadIdx.x == 0) red[0] = t;
    }
    __syncthreads();
    float r = red[0];
    __syncthreads();
    return r;
}

__global__ __launch_bounds__(256)
void layernorm_kernel(const float* __restrict__ in, const float* __restrict__ g,
                      const float* __restrict__ beta, float* __restrict__ out)
{
    __shared__ float red[8];
    const int row = blockIdx.x;
    const int tid = threadIdx.x;
    float4 v = ((const float4*)(in + (size_t)row * EMB))[tid];
    float mean = block_sum_1024(v.x + v.y + v.z + v.w, red) * (1.f / EMB);
    float dx = v.x - mean, dy = v.y - mean, dz = v.z - mean, dw = v.w - mean;
    float var = block_sum_1024(dx * dx + dy * dy + dz * dz + dw * dw, red) * (1.f / EMB);
    float rstd = rsqrtf(var + 1e-5f);
    float4 gv = ((const float4*)g)[tid];
    float4 bv = ((const float4*)beta)[tid];
    float4 o;
    o.x = dx * rstd * gv.x + bv.x;
    o.y = dy * rstd * gv.y + bv.y;
    o.z = dz * rstd * gv.z + bv.z;
    o.w = dw * rstd * gv.w + bv.w;
    ((float4*)(out + (size_t)row * EMB))[tid] = o;
}

// ---------------------------------------------------------------------------
// Causal flash attention, fp32 (unchanged from R7 passing kernel)
// ---------------------------------------------------------------------------
struct AttnSmem {
    float Qs[64][68];
    float Ks[64][68];
    float Vs[64][68];
    float Ss[64][68];
    float Pt[64][68];
    float mrow[64];
    float lrow[64];
    float arow[64];
};

#define DOT4(a, b) ((a).x*(b).x + (a).y*(b).y + (a).z*(b).z + (a).w*(b).w)

__global__ __launch_bounds__(256, 1)
void attn_kernel(const float* __restrict__ qkv, float* __restrict__ z)
{
    extern __shared__ char smem_raw[];
    AttnSmem& sm = *reinterpret_cast<AttnSmem*>(smem_raw);

    const int qb = blockIdx.x;
    const int h  = blockIdx.y;
    const int b  = blockIdx.z;
    const int tid = threadIdx.x;
    const int tx = tid & 15, ty = tid >> 4;
    const size_t rs = N3E;
    const float scale = 0.125f;

    const float* qbase = qkv + (size_t)(b * LSEQ + qb * 64) * rs + h * 64;
#pragma unroll
    for (int it = 0; it < 4; ++it) {
        int idx = tid + it * 256;
        int r = idx >> 4, c4 = (idx & 15) << 2;
        float4 v = *(const float4*)(qbase + (size_t)r * rs + c4);
        sm.Qs[r][c4 + 0] = v.x * scale;
        sm.Qs[r][c4 + 1] = v.y * scale;
        sm.Qs[r][c4 + 2] = v.z * scale;
        sm.Qs[r][c4 + 3] = v.w * scale;
    }
    if (tid < 64) { sm.mrow[tid] = -1e30f; sm.lrow[tid] = 0.f; }

    float acc[4][4];
#pragma unroll
    for (int i = 0; i < 4; ++i)
#pragma unroll
        for (int j = 0; j < 4; ++j) acc[i][j] = 0.f;

    for (int kb = 0; kb <= qb; ++kb) {
        __syncthreads();

        const float* kbase = qkv + (size_t)(b * LSEQ + kb * 64) * rs + EMB + h * 64;
        const float* vbase = kbase + EMB;
#pragma unroll
        for (int it = 0; it < 4; ++it) {
            int idx = tid + it * 256;
            int r = idx >> 4, c4 = (idx & 15) << 2;
            float4 kv = *(const float4*)(kbase + (size_t)r * rs + c4);
            sm.Ks[r][c4 + 0] = kv.x; sm.Ks[r][c4 + 1] = kv.y;
            sm.Ks[r][c4 + 2] = kv.z; sm.Ks[r][c4 + 3] = kv.w;
            float4 vv = *(const float4*)(vbase + (size_t)r * rs + c4);
            sm.Vs[r][c4 + 0] = vv.x; sm.Vs[r][c4 + 1] = vv.y;
            sm.Vs[r][c4 + 2] = vv.z; sm.Vs[r][c4 + 3] = vv.w;
        }
        __syncthreads();

        float s[4][4];
#pragma unroll
        for (int i = 0; i < 4; ++i)
#pragma unroll
            for (int j = 0; j < 4; ++j) s[i][j] = 0.f;
#pragma unroll
        for (int d4 = 0; d4 < 64; d4 += 4) {
            float4 q0 = *(const float4*)&sm.Qs[ty     ][d4];
            float4 q1 = *(const float4*)&sm.Qs[ty + 16][d4];
            float4 q2 = *(const float4*)&sm.Qs[ty + 32][d4];
            float4 q3 = *(const float4*)&sm.Qs[ty + 48][d4];
            float4 k0 = *(const float4*)&sm.Ks[tx     ][d4];
            float4 k1 = *(const float4*)&sm.Ks[tx + 16][d4];
            float4 k2 = *(const float4*)&sm.Ks[tx + 32][d4];
            float4 k3 = *(const float4*)&sm.Ks[tx + 48][d4];
            s[0][0] += DOT4(q0,k0); s[0][1] += DOT4(q0,k1); s[0][2] += DOT4(q0,k2); s[0][3] += DOT4(q0,k3);
            s[1][0] += DOT4(q1,k0); s[1][1] += DOT4(q1,k1); s[1][2] += DOT4(q1,k2); s[1][3] += DOT4(q1,k3);
            s[2][0] += DOT4(q2,k0); s[2][1] += DOT4(q2,k1); s[2][2] += DOT4(q2,k2); s[2][3] += DOT4(q2,k3);
            s[3][0] += DOT4(q3,k0); s[3][1] += DOT4(q3,k1); s[3][2] += DOT4(q3,k2); s[3][3] += DOT4(q3,k3);
        }
#pragma unroll
        for (int ii = 0; ii < 4; ++ii)
#pragma unroll
            for (int jj = 0; jj < 4; ++jj)
                sm.Ss[ty + 16 * ii][tx + 16 * jj] = s[ii][jj];
        __syncthreads();

        if (tid < 64) {
            const int r = tid;
            const bool diag = (kb == qb);
            float m_old = sm.mrow[r];
            float mmax = m_old;
#pragma unroll
            for (int j4 = 0; j4 < 64; j4 += 4) {
                float4 v = *(const float4*)&sm.Ss[r][j4];
                if (diag) {
                    if (j4 + 0 > r) v.x = -1e30f;
                    if (j4 + 1 > r) v.y = -1e30f;
                    if (j4 + 2 > r) v.z = -1e30f;
                    if (j4 + 3 > r) v.w = -1e30f;
                }
                mmax = fmaxf(mmax, fmaxf(fmaxf(v.x, v.y), fmaxf(v.z, v.w)));
            }
            float alpha = expf(m_old - mmax);
            float lsum = 0.f;
#pragma unroll
            for (int j4 = 0; j4 < 64; j4 += 4) {
                float4 v = *(const float4*)&sm.Ss[r][j4];
                float p0 = (diag && (j4 + 0 > r)) ? 0.f : expf(v.x - mmax);
                float p1 = (diag && (j4 + 1 > r)) ? 0.f : expf(v.y - mmax);
                float p2 = (diag && (j4 + 2 > r)) ? 0.f : expf(v.z - mmax);
                float p3 = (diag && (j4 + 3 > r)) ? 0.f : expf(v.w - mmax);
                sm.Pt[j4 + 0][r] = p0;
                sm.Pt[j4 + 1][r] = p1;
                sm.Pt[j4 + 2][r] = p2;
                sm.Pt[j4 + 3][r] = p3;
                lsum += p0 + p1 + p2 + p3;
            }
            sm.mrow[r] = mmax;
            sm.lrow[r] = sm.lrow[r] * alpha + lsum;
            sm.arow[r] = alpha;
        }
        __syncthreads();

        float a0 = sm.arow[ty], a1 = sm.arow[ty + 16];
        float a2 = sm.arow[ty + 32], a3 = sm.arow[ty + 48];
#pragma unroll
        for (int jj = 0; jj < 4; ++jj) {
            acc[0][jj] *= a0; acc[1][jj] *= a1;
            acc[2][jj] *= a2; acc[3][jj] *= a3;
        }
#pragma unroll 16
        for (int k = 0; k < 64; ++k) {
            float p0 = sm.Pt[k][ty],      p1 = sm.Pt[k][ty + 16];
            float p2 = sm.Pt[k][ty + 32], p3 = sm.Pt[k][ty + 48];
            float v0 = sm.Vs[k][tx],      v1 = sm.Vs[k][tx + 16];
            float v2 = sm.Vs[k][tx + 32], v3 = sm.Vs[k][tx + 48];
            acc[0][0] += p0 * v0; acc[0][1] += p0 * v1; acc[0][2] += p0 * v2; acc[0][3] += p0 * v3;
            acc[1][0] += p1 * v0; acc[1][1] += p1 * v1; acc[1][2] += p1 * v2; acc[1][3] += p1 * v3;
            acc[2][0] += p2 * v0; acc[2][1] += p2 * v1; acc[2][2] += p2 * v2; acc[2][3] += p2 * v3;
            acc[3][0] += p3 * v0; acc[3][1] += p3 * v1; acc[3][2] += p3 * v2; acc[3][3] += p3 * v3;
        }
    }

    float inv[4];
    inv[0] = 1.f / sm.lrow[ty];      inv[1] = 1.f / sm.lrow[ty + 16];
    inv[2] = 1.f / sm.lrow[ty + 32]; inv[3] = 1.f / sm.lrow[ty + 48];
    float* zb = z + (size_t)(b * LSEQ + qb * 64) * EMB + h * 64;
#pragma unroll
    for (int ii = 0; ii < 4; ++ii) {
        int i = ty + 16 * ii;
#pragma unroll
        for (int jj = 0; jj < 4; ++jj)
            zb[(size_t)i * EMB + tx + 16 * jj] = acc[ii][jj] * inv[ii];
    }
}

// ---------------------------------------------------------------------------
// Launch
// ---------------------------------------------------------------------------
extern "C" void kernel_launch(void* const* d_in, const int* in_sizes, int n_in,
                              void* d_out, int out_size)
{
    const float* x   = (const float*)d_in[0];
    const float* Wq  = (const float*)d_in[2];
    const float* bq  = (const float*)d_in[3];
    const float* Wk  = (const float*)d_in[4];
    const float* bk  = (const float*)d_in[5];
    const float* Wv  = (const float*)d_in[6];
    const float* bv  = (const float*)d_in[7];
    const float* Wo  = (const float*)d_in[8];
    const float* bo  = (const float*)d_in[9];
    const float* W1  = (const float*)d_in[10];
    const float* c1  = (const float*)d_in[11];
    const float* W2  = (const float*)d_in[12];
    const float* c2  = (const float*)d_in[13];
    const float* g1  = (const float*)d_in[14];
    const float* be1 = (const float*)d_in[15];
    const float* g2  = (const float*)d_in[16];
    const float* be2 = (const float*)d_in[17];
    float* out = (float*)d_out;

    float *wqkv, *bqkv, *qkv, *zz, *t1, *hh, *ff;
    cudaGetSymbolAddress((void**)&wqkv, g_wqkv);
    cudaGetSymbolAddress((void**)&bqkv, g_bqkv);
    cudaGetSymbolAddress((void**)&qkv,  g_qkv);
    cudaGetSymbolAddress((void**)&zz,   g_z);
    cudaGetSymbolAddress((void**)&t1,   g_t1);
    cudaGetSymbolAddress((void**)&hh,   g_h);
    cudaGetSymbolAddress((void**)&ff,   g_ff);

    cudaFuncSetAttribute(attn_kernel, cudaFuncAttributeMaxDynamicSharedMemorySize,
                         (int)sizeof(AttnSmem));
    cudaFuncSetAttribute(bgemm<false, false>, cudaFuncAttributeMaxDynamicSharedMemorySize, GEMM_SMEM);
    cudaFuncSetAttribute(bgemm<false, true>,  cudaFuncAttributeMaxDynamicSharedMemorySize, GEMM_SMEM);
    cudaFuncSetAttribute(bgemm<true, false>,  cudaFuncAttributeMaxDynamicSharedMemorySize, GEMM_SMEM);

    // 1. pack QKV weights/biases
    pack_qkv_kernel<<<(EMB * N3E + 255) / 256, 256>>>(Wq, Wk, Wv, bq, bk, bv);

    // 2. qkv = x @ Wqkv + b   (4096 x 3072, K=1024)
    bgemm<false, false><<<dim3(N3E / 128, MR / 128), 256, GEMM_SMEM>>>(
        x, wqkv, bqkv, nullptr, qkv, MR, N3E, EMB);

    // 3. causal attention -> z
    attn_kernel<<<dim3(LSEQ / 64, HN, BSZ), 256, sizeof(AttnSmem)>>>(qkv, zz);

    // 4. t1 = z @ Wo + bo + x
    bgemm<false, true><<<dim3(EMB / 128, MR / 128), 256, GEMM_SMEM>>>(
        zz, Wo, bo, x, t1, MR, EMB, EMB);

    // 5. h = LN1(t1)
    layernorm_kernel<<<MR, 256>>>(t1, g1, be1, hh);

    // 6. ff = relu(h @ W1 + c1)   (4096 x 4096, K=1024)
    bgemm<true, false><<<dim3(DFF / 128, MR / 128), 256, GEMM_SMEM>>>(
        hh, W1, c1, nullptr, ff, MR, DFF, EMB);

    // 7. t1 = ff @ W2 + c2 + h   (4096 x 1024, K=4096)
    bgemm<false, true><<<dim3(EMB / 128, MR / 128), 256, GEMM_SMEM>>>(
        ff, W2, c2, hh, t1, MR, EMB, DFF);

    // 8. out = LN2(t1)
    layernorm_kernel<<<MR, 256>>>(t1, g2, be2, out);
}

// round 12
// speedup vs baseline: 1.3188x; 1.0899x over previous
#include <cuda_runtime.h>
#include <cuda_bf16.h>
#include <mma.h>
#include <math.h>
#include <stdint.h>

using namespace nvcuda;

// Problem constants
#define BSZ  2
#define LSEQ 2048
#define EMB  1024
#define HN   16
#define DHD  64
#define DFF  4096
#define MR   (BSZ*LSEQ)     // 4096
#define N3E  (3*EMB)        // 3072

// ---------------------------------------------------------------------------
// Scratch
// ---------------------------------------------------------------------------
__device__ float g_bqkv[N3E];
__device__ float g_qkv[(size_t)MR * N3E];
__device__ float g_t1 [(size_t)MR * EMB];
__device__ float g_h  [(size_t)MR * EMB];

// bf16 hi/lo operands
__device__ __nv_bfloat16 g_xh [(size_t)MR * EMB], g_xl [(size_t)MR * EMB];
__device__ __nv_bfloat16 g_zh [(size_t)MR * EMB], g_zl [(size_t)MR * EMB];
__device__ __nv_bfloat16 g_hh [(size_t)MR * EMB], g_hl [(size_t)MR * EMB];
__device__ __nv_bfloat16 g_ffh[(size_t)MR * DFF], g_ffl[(size_t)MR * DFF];
__device__ __nv_bfloat16 g_wqkvh[(size_t)EMB * N3E], g_wqkvl[(size_t)EMB * N3E];
__device__ __nv_bfloat16 g_woh[(size_t)EMB * EMB],  g_wol[(size_t)EMB * EMB];
__device__ __nv_bfloat16 g_w1h[(size_t)EMB * DFF],  g_w1l[(size_t)EMB * DFF];
__device__ __nv_bfloat16 g_w2h[(size_t)DFF * EMB],  g_w2l[(size_t)DFF * EMB];

// ---------------------------------------------------------------------------
// helpers
// ---------------------------------------------------------------------------
__device__ __forceinline__ uint32_t smem_u32(const void* p) {
    uint32_t a;
    asm("{ .reg .u64 t; cvta.to.shared.u64 t, %1; cvt.u32.u64 %0, t; }" : "=r"(a) : "l"(p));
    return a;
}
#define CP_ASYNC(dst, src) asm volatile("cp.async.cg.shared.global [%0], [%1], 16;" :: "r"(dst), "l"(src))
#define CP_COMMIT()        asm volatile("cp.async.commit_group;" ::: "memory")
#define CP_WAIT(n)         asm volatile("cp.async.wait_group %0;" :: "n"(n) : "memory")

__device__ __forceinline__ void split2(float v, __nv_bfloat16& h, __nv_bfloat16& l) {
    h = __float2bfloat16(v);
    l = __float2bfloat16(v - __bfloat162float(h));
}

// ---------------------------------------------------------------------------
// generic fp32 -> bf16 hi/lo split (elementwise, float4)
// ---------------------------------------------------------------------------
__global__ void split_kernel(const float* __restrict__ src, __nv_bfloat16* __restrict__ h,
                             __nv_bfloat16* __restrict__ l, int n4)
{
    int i = blockIdx.x * blockDim.x + threadIdx.x;
    if (i >= n4) return;
    float4 v = ((const float4*)src)[i];
    __nv_bfloat162 h01, h23, l01, l23;
    split2(v.x, h01.x, l01.x); split2(v.y, h01.y, l01.y);
    split2(v.z, h23.x, l23.x); split2(v.w, h23.y, l23.y);
    uint2 hv, lv;
    hv.x = *(uint32_t*)&h01; hv.y = *(uint32_t*)&h23;
    lv.x = *(uint32_t*)&l01; lv.y = *(uint32_t*)&l23;
    ((uint2*)h)[i] = hv;
    ((uint2*)l)[i] = lv;
}

// pack Wq/Wk/Wv (H,E,Dh) -> [E][3E] bf16 hi/lo; biases -> g_bqkv
__global__ void pack_qkv_split(const float* __restrict__ Wq, const float* __restrict__ Wk,
                               const float* __restrict__ Wv, const float* __restrict__ bq,
                               const float* __restrict__ bk, const float* __restrict__ bv)
{
    int idx = blockIdx.x * blockDim.x + threadIdx.x;
    if (idx < EMB * N3E) {
        int n = idx % N3E, e = idx / N3E;
        int proj = n / EMB, hd = n % EMB;
        const float* W = (proj == 0) ? Wq : (proj == 1) ? Wk : Wv;
        float v = W[(size_t)(hd >> 6) * EMB * DHD + (size_t)e * DHD + (hd & 63)];
        __nv_bfloat16 h, l; split2(v, h, l);
        g_wqkvh[idx] = h; g_wqkvl[idx] = l;
    }
    if (idx < N3E) {
        int proj = idx / EMB, hd = idx % EMB;
        const float* bb = (proj == 0) ? bq : (proj == 1) ? bk : bv;
        g_bqkv[idx] = bb[hd];
    }
}

// ---------------------------------------------------------------------------
// bf16x3 WMMA GEMM with cp.async 3-stage pipeline.
// CTA 128x128, BK=32, 128 threads (4 warps, 2x2), warp tile 64x64.
// A: [M][K] bf16 hi/lo row-major. B: [K][N] bf16 hi/lo row-major.
// smem per stage (bytes): AH@0 (128x40x2=10240) | AL@10240 | BH@20480 (32x136x2=8704) | BL@29184
// stage size 37888, 3 stages = 113664 bytes.
// ---------------------------------------------------------------------------
#define STG       37888
#define GEMM_SMEM (3 * STG)

__device__ __forceinline__ void issue_tile(uint32_t sbase,
    const __nv_bfloat16* __restrict__ Ah, const __nv_bfloat16* __restrict__ Al,
    const __nv_bfloat16* __restrict__ Bh, const __nv_bfloat16* __restrict__ Bl,
    int K, int N, int m0, int n0, int kt, int tid)
{
    // A: thread t loads row t, 4x8 bf16 chunks
    const __nv_bfloat16* pah = Ah + (size_t)(m0 + tid) * K + kt;
    const __nv_bfloat16* pal = Al + (size_t)(m0 + tid) * K + kt;
    uint32_t da  = sbase + tid * 80;
    uint32_t dal = sbase + 10240 + tid * 80;
#pragma unroll
    for (int i = 0; i < 4; ++i) CP_ASYNC(da  + i * 16, pah + i * 8);
#pragma unroll
    for (int i = 0; i < 4; ++i) CP_ASYNC(dal + i * 16, pal + i * 8);
    // B: thread t -> row t>>2, col chunks (t&3) + i*4
    int br = tid >> 2, bc = tid & 3;
    const __nv_bfloat16* pbh = Bh + (size_t)(kt + br) * N + n0 + bc * 8;
    const __nv_bfloat16* pbl = Bl + (size_t)(kt + br) * N + n0 + bc * 8;
    uint32_t db  = sbase + 20480 + br * 272 + bc * 16;
    uint32_t dbl = sbase + 29184 + br * 272 + bc * 16;
#pragma unroll
    for (int i = 0; i < 4; ++i) CP_ASYNC(db  + i * 64, pbh + i * 32);
#pragma unroll
    for (int i = 0; i < 4; ++i) CP_ASYNC(dbl + i * 64, pbl + i * 32);
}

template<bool RELU, bool ADDRES, bool SPLITOUT>
__global__ __launch_bounds__(128)
void bgemm(const __nv_bfloat16* __restrict__ Ah, const __nv_bfloat16* __restrict__ Al,
           const __nv_bfloat16* __restrict__ Bh, const __nv_bfloat16* __restrict__ Bl,
           const float* __restrict__ bias, const float* __restrict__ res,
           float* __restrict__ C, __nv_bfloat16* __restrict__ Chi,
           __nv_bfloat16* __restrict__ Clo, int M, int N, int K)
{
    extern __shared__ char smem[];
    const uint32_t sb = smem_u32(smem);
    const int tid = threadIdx.x;
    const int wid = tid >> 5;
    const int wm = wid >> 1, wn = wid & 1;     // 2x2 warp grid, 64x64 tiles
    const int bx = blockIdx.x, by = blockIdx.y;
    const int m0 = by * 128, n0 = bx * 128;
    const int NT = K / 32;

    wmma::fragment<wmma::accumulator, 16, 16, 16, float> acc[4][4];
#pragma unroll
    for (int i = 0; i < 4; ++i)
#pragma unroll
        for (int j = 0; j < 4; ++j) wmma::fill_fragment(acc[i][j], 0.f);

    // prologue: 3 stages
#pragma unroll
    for (int s = 0; s < 3; ++s) {
        issue_tile(sb + s * STG, Ah, Al, Bh, Bl, K, N, m0, n0, s * 32, tid);
        CP_COMMIT();
    }

    for (int t = 0; t < NT; ++t) {
        CP_WAIT(2);
        __syncthreads();

        const int buf = t % 3;
        const __nv_bfloat16* AHs = (const __nv_bfloat16*)(smem + buf * STG);
        const __nv_bfloat16* ALs = (const __nv_bfloat16*)(smem + buf * STG + 10240);
        const __nv_bfloat16* BHs = (const __nv_bfloat16*)(smem + buf * STG + 20480);
        const __nv_bfloat16* BLs = (const __nv_bfloat16*)(smem + buf * STG + 29184);

#pragma unroll
        for (int ks = 0; ks < 2; ++ks) {
            wmma::fragment<wmma::matrix_a, 16, 16, 16, __nv_bfloat16, wmma::row_major> fah[4], fal[4];
#pragma unroll
            for (int i = 0; i < 4; ++i) {
                int off = (wm * 64 + i * 16) * 40 + ks * 16;
                wmma::load_matrix_sync(fah[i], AHs + off, 40);
                wmma::load_matrix_sync(fal[i], ALs + off, 40);
            }
#pragma unroll
            for (int j = 0; j < 4; ++j) {
                wmma::fragment<wmma::matrix_b, 16, 16, 16, __nv_bfloat16, wmma::row_major> fbh, fbl;
                int off = (ks * 16) * 136 + wn * 64 + j * 16;
                wmma::load_matrix_sync(fbh, BHs + off, 136);
                wmma::load_matrix_sync(fbl, BLs + off, 136);
#pragma unroll
                for (int i = 0; i < 4; ++i) {
                    wmma::mma_sync(acc[i][j], fah[i], fbh, acc[i][j]);
                    wmma::mma_sync(acc[i][j], fah[i], fbl, acc[i][j]);
                    wmma::mma_sync(acc[i][j], fal[i], fbh, acc[i][j]);
                }
            }
        }

        __syncthreads();
        if (t + 3 < NT)
            issue_tile(sb + buf * STG, Ah, Al, Bh, Bl, K, N, m0, n0, (t + 3) * 32, tid);
        CP_COMMIT();
    }

    CP_WAIT(0);
    __syncthreads();

    // stage accumulators to smem: per-warp 64x68 f32 region (17408 B)
    float* Cs = (float*)smem;
    float* wbase = Cs + wid * 4352;
#pragma unroll
    for (int i = 0; i < 4; ++i)
#pragma unroll
        for (int j = 0; j < 4; ++j)
            wmma::store_matrix_sync(wbase + (i * 16) * 68 + j * 16, acc[i][j], 68,
                                    wmma::mem_row_major);
    __syncthreads();

    // fused output: thread t handles row t
    {
        const int m = m0 + tid;
        const float* bp = bias + n0;
        const float* rp = ADDRES ? (res + (size_t)m * N + n0) : nullptr;
#pragma unroll 8
        for (int cb = 0; cb < 128; cb += 4) {
            int w = ((tid >> 6) << 1) | (cb >> 6);
            const float* sp = Cs + w * 4352 + (tid & 63) * 68 + (cb & 63);
            float4 v = *(const float4*)sp;
            float4 bi = *(const float4*)(bp + cb);
            v.x += bi.x; v.y += bi.y; v.z += bi.z; v.w += bi.w;
            if (ADDRES) {
                float4 rr = *(const float4*)(rp + cb);
                v.x += rr.x; v.y += rr.y; v.z += rr.z; v.w += rr.w;
            }
            if (RELU) {
                v.x = fmaxf(v.x, 0.f); v.y = fmaxf(v.y, 0.f);
                v.z = fmaxf(v.z, 0.f); v.w = fmaxf(v.w, 0.f);
            }
            if (SPLITOUT) {
                __nv_bfloat162 h01, h23, l01, l23;
                split2(v.x, h01.x, l01.x); split2(v.y, h01.y, l01.y);
                split2(v.z, h23.x, l23.x); split2(v.w, h23.y, l23.y);
                uint2 hv, lv;
                hv.x = *(uint32_t*)&h01; hv.y = *(uint32_t*)&h23;
                lv.x = *(uint32_t*)&l01; lv.y = *(uint32_t*)&l23;
                *(uint2*)&Chi[(size_t)m * N + n0 + cb] = hv;
                *(uint2*)&Clo[(size_t)m * N + n0 + cb] = lv;
            } else {
                *(float4*)&C[(size_t)m * N + n0 + cb] = v;
            }
        }
    }
}

// ---------------------------------------------------------------------------
// LayerNorm (optional split output)
// ---------------------------------------------------------------------------
__device__ __forceinline__ float block_sum_1024(float v, float* red)
{
#pragma unroll
    for (int o = 16; o; o >>= 1) v += __shfl_xor_sync(0xffffffffu, v, o);
    int w = threadIdx.x >> 5;
    if ((threadIdx.x & 31) == 0) red[w] = v;
    __syncthreads();
    if (threadIdx.x < 32) {
        float t = (threadIdx.x < 8) ? red[threadIdx.x] : 0.f;
#pragma unroll
        for (int o = 4; o; o >>= 1) t += __shfl_xor_sync(0xffffffffu, t, o);
        if (threadIdx.x == 0) red[0] = t;
    }
    __syncthreads();
    float r = red[0];
    __syncthreads();
    return r;
}

template<bool SPLIT>
__global__ __launch_bounds__(256)
void layernorm_kernel(const float* __restrict__ in, const float* __restrict__ g,
                      const float* __restrict__ beta, float* __restrict__ out,
                      __nv_bfloat16* __restrict__ oh, __nv_bfloat16* __restrict__ ol)
{
    __shared__ float red[8];
    const int row = blockIdx.x;
    const int tid = threadIdx.x;
    float4 v = ((const float4*)(in + (size_t)row * EMB))[tid];
    float mean = block_sum_1024(v.x + v.y + v.z + v.w, red) * (1.f / EMB);
    float dx = v.x - mean, dy = v.y - mean, dz = v.z - mean, dw = v.w - mean;
    float var = block_sum_1024(dx * dx + dy * dy + dz * dz + dw * dw, red) * (1.f / EMB);
    float rstd = rsqrtf(var + 1e-5f);
    float4 gv = ((const float4*)g)[tid];
    float4 bv = ((const float4*)beta)[tid];
    float4 o;
    o.x = dx * rstd * gv.x + bv.x;
    o.y = dy * rstd * gv.y + bv.y;
    o.z = dz * rstd * gv.z + bv.z;
    o.w = dw * rstd * gv.w + bv.w;
    ((float4*)(out + (size_t)row * EMB))[tid] = o;
    if (SPLIT) {
        __nv_bfloat162 h01, h23, l01, l23;
        split2(o.x, h01.x, l01.x); split2(o.y, h01.y, l01.y);
        split2(o.z, h23.x, l23.x); split2(o.w, h23.y, l23.y);
        uint2 hv, lv;
        hv.x = *(uint32_t*)&h01; hv.y = *(uint32_t*)&h23;
        lv.x = *(uint32_t*)&l01; lv.y = *(uint32_t*)&l23;
        ((uint2*)(oh + (size_t)row * EMB))[tid] = hv;
        ((uint2*)(ol + (size_t)row * EMB))[tid] = lv;
    }
}

// ---------------------------------------------------------------------------
// Causal flash attention, fp32; final store writes zh/zl splits
// ---------------------------------------------------------------------------
struct AttnSmem {
    float Qs[64][68];
    float Ks[64][68];
    float Vs[64][68];
    float Ss[64][68];
    float Pt[64][68];
    float mrow[64];
    float lrow[64];
    float arow[64];
};

#define DOT4(a, b) ((a).x*(b).x + (a).y*(b).y + (a).z*(b).z + (a).w*(b).w)

__global__ __launch_bounds__(256, 1)
void attn_kernel(const float* __restrict__ qkv, __nv_bfloat16* __restrict__ zh,
                 __nv_bfloat16* __restrict__ zl)
{
    extern __shared__ char smem_raw[];
    AttnSmem& sm = *reinterpret_cast<AttnSmem*>(smem_raw);

    const int qb = blockIdx.x, h = blockIdx.y, b = blockIdx.z;
    const int tid = threadIdx.x;
    const int tx = tid & 15, ty = tid >> 4;
    const size_t rs = N3E;
    const float scale = 0.125f;

    const float* qbase = qkv + (size_t)(b * LSEQ + qb * 64) * rs + h * 64;
#pragma unroll
    for (int it = 0; it < 4; ++it) {
        int idx = tid + it * 256;
        int r = idx >> 4, c4 = (idx & 15) << 2;
        float4 v = *(const float4*)(qbase + (size_t)r * rs + c4);
        sm.Qs[r][c4 + 0] = v.x * scale; sm.Qs[r][c4 + 1] = v.y * scale;
        sm.Qs[r][c4 + 2] = v.z * scale; sm.Qs[r][c4 + 3] = v.w * scale;
    }
    if (tid < 64) { sm.mrow[tid] = -1e30f; sm.lrow[tid] = 0.f; }

    float acc[4][4];
#pragma unroll
    for (int i = 0; i < 4; ++i)
#pragma unroll
        for (int j = 0; j < 4; ++j) acc[i][j] = 0.f;

    for (int kb = 0; kb <= qb; ++kb) {
        __syncthreads();
        const float* kbase = qkv + (size_t)(b * LSEQ + kb * 64) * rs + EMB + h * 64;
        const float* vbase = kbase + EMB;
#pragma unroll
        for (int it = 0; it < 4; ++it) {
            int idx = tid + it * 256;
            int r = idx >> 4, c4 = (idx & 15) << 2;
            float4 kv = *(const float4*)(kbase + (size_t)r * rs + c4);
            sm.Ks[r][c4 + 0] = kv.x; sm.Ks[r][c4 + 1] = kv.y;
            sm.Ks[r][c4 + 2] = kv.z; sm.Ks[r][c4 + 3] = kv.w;
            float4 vv = *(const float4*)(vbase + (size_t)r * rs + c4);
            sm.Vs[r][c4 + 0] = vv.x; sm.Vs[r][c4 + 1] = vv.y;
            sm.Vs[r][c4 + 2] = vv.z; sm.Vs[r][c4 + 3] = vv.w;
        }
        __syncthreads();

        float s[4][4];
#pragma unroll
        for (int i = 0; i < 4; ++i)
#pragma unroll
            for (int j = 0; j < 4; ++j) s[i][j] = 0.f;
#pragma unroll
        for (int d4 = 0; d4 < 64; d4 += 4) {
            float4 q0 = *(const float4*)&sm.Qs[ty     ][d4];
            float4 q1 = *(const float4*)&sm.Qs[ty + 16][d4];
            float4 q2 = *(const float4*)&sm.Qs[ty + 32][d4];
            float4 q3 = *(const float4*)&sm.Qs[ty + 48][d4];
            float4 k0 = *(const float4*)&sm.Ks[tx     ][d4];
            float4 k1 = *(const float4*)&sm.Ks[tx + 16][d4];
            float4 k2 = *(const float4*)&sm.Ks[tx + 32][d4];
            float4 k3 = *(const float4*)&sm.Ks[tx + 48][d4];
            s[0][0] += DOT4(q0,k0); s[0][1] += DOT4(q0,k1); s[0][2] += DOT4(q0,k2); s[0][3] += DOT4(q0,k3);
            s[1][0] += DOT4(q1,k0); s[1][1] += DOT4(q1,k1); s[1][2] += DOT4(q1,k2); s[1][3] += DOT4(q1,k3);
            s[2][0] += DOT4(q2,k0); s[2][1] += DOT4(q2,k1); s[2][2] += DOT4(q2,k2); s[2][3] += DOT4(q2,k3);
            s[3][0] += DOT4(q3,k0); s[3][1] += DOT4(q3,k1); s[3][2] += DOT4(q3,k2); s[3][3] += DOT4(q3,k3);
        }
#pragma unroll
        for (int ii = 0; ii < 4; ++ii)
#pragma unroll
            for (int jj = 0; jj < 4; ++jj)
                sm.Ss[ty + 16 * ii][tx + 16 * jj] = s[ii][jj];
        __syncthreads();

        if (tid < 64) {
            const int r = tid;
            const bool diag = (kb == qb);
            float m_old = sm.mrow[r];
            float mmax = m_old;
#pragma unroll
            for (int j4 = 0; j4 < 64; j4 += 4) {
                float4 v = *(const float4*)&sm.Ss[r][j4];
                if (diag) {
                    if (j4 + 0 > r) v.x = -1e30f;
                    if (j4 + 1 > r) v.y = -1e30f;
                    if (j4 + 2 > r) v.z = -1e30f;
                    if (j4 + 3 > r) v.w = -1e30f;
                }
                mmax = fmaxf(mmax, fmaxf(fmaxf(v.x, v.y), fmaxf(v.z, v.w)));
            }
            float alpha = expf(m_old - mmax);
            float lsum = 0.f;
#pragma unroll
            for (int j4 = 0; j4 < 64; j4 += 4) {
                float4 v = *(const float4*)&sm.Ss[r][j4];
                float p0 = (diag && (j4 + 0 > r)) ? 0.f : expf(v.x - mmax);
                float p1 = (diag && (j4 + 1 > r)) ? 0.f : expf(v.y - mmax);
                float p2 = (diag && (j4 + 2 > r)) ? 0.f : expf(v.z - mmax);
                float p3 = (diag && (j4 + 3 > r)) ? 0.f : expf(v.w - mmax);
                sm.Pt[j4 + 0][r] = p0; sm.Pt[j4 + 1][r] = p1;
                sm.Pt[j4 + 2][r] = p2; sm.Pt[j4 + 3][r] = p3;
                lsum += p0 + p1 + p2 + p3;
            }
            sm.mrow[r] = mmax;
            sm.lrow[r] = sm.lrow[r] * alpha + lsum;
            sm.arow[r] = alpha;
        }
        __syncthreads();

        float a0 = sm.arow[ty], a1 = sm.arow[ty + 16];
        float a2 = sm.arow[ty + 32], a3 = sm.arow[ty + 48];
#pragma unroll
        for (int jj = 0; jj < 4; ++jj) {
            acc[0][jj] *= a0; acc[1][jj] *= a1;
            acc[2][jj] *= a2; acc[3][jj] *= a3;
        }
#pragma unroll 16
        for (int k = 0; k < 64; ++k) {
            float p0 = sm.Pt[k][ty],      p1 = sm.Pt[k][ty + 16];
            float p2 = sm.Pt[k][ty + 32], p3 = sm.Pt[k][ty + 48];
            float v0 = sm.Vs[k][tx],      v1 = sm.Vs[k][tx + 16];
            float v2 = sm.Vs[k][tx + 32], v3 = sm.Vs[k][tx + 48];
            acc[0][0] += p0 * v0; acc[0][1] += p0 * v1; acc[0][2] += p0 * v2; acc[0][3] += p0 * v3;
            acc[1][0] += p1 * v0; acc[1][1] += p1 * v1; acc[1][2] += p1 * v2; acc[1][3] += p1 * v3;
            acc[2][0] += p2 * v0; acc[2][1] += p2 * v1; acc[2][2] += p2 * v2; acc[2][3] += p2 * v3;
            acc[3][0] += p3 * v0; acc[3][1] += p3 * v1; acc[3][2] += p3 * v2; acc[3][3] += p3 * v3;
        }
    }

    float inv[4];
    inv[0] = 1.f / sm.lrow[ty];      inv[1] = 1.f / sm.lrow[ty + 16];
    inv[2] = 1.f / sm.lrow[ty + 32]; inv[3] = 1.f / sm.lrow[ty + 48];
    const int mbase = b * LSEQ + qb * 64;
#pragma unroll
    for (int ii = 0; ii < 4; ++ii) {
        int m = mbase + ty + 16 * ii;
#pragma unroll
        for (int jj = 0; jj < 4; ++jj) {
            float val = acc[ii][jj] * inv[ii];
            __nv_bfloat16 hb, lb; split2(val, hb, lb);
            size_t off = (size_t)m * EMB + h * 64 + tx + 16 * jj;
            zh[off] = hb;
            zl[off] = lb;
        }
    }
}

// ---------------------------------------------------------------------------
// Launch
// ---------------------------------------------------------------------------
extern "C" void kernel_launch(void* const* d_in, const int* in_sizes, int n_in,
                              void* d_out, int out_size)
{
    const float* x   = (const float*)d_in[0];
    const float* Wq  = (const float*)d_in[2];
    const float* bq  = (const float*)d_in[3];
    const float* Wk  = (const float*)d_in[4];
    const float* bk  = (const float*)d_in[5];
    const float* Wv  = (const float*)d_in[6];
    const float* bv  = (const float*)d_in[7];
    const float* Wo  = (const float*)d_in[8];
    const float* bo  = (const float*)d_in[9];
    const float* W1  = (const float*)d_in[10];
    const float* c1  = (const float*)d_in[11];
    const float* W2  = (const float*)d_in[12];
    const float* c2  = (const float*)d_in[13];
    const float* g1  = (const float*)d_in[14];
    const float* be1 = (const float*)d_in[15];
    const float* g2  = (const float*)d_in[16];
    const float* be2 = (const float*)d_in[17];
    float* out = (float*)d_out;

    float *bqkv, *qkv, *t1, *hbuf;
    __nv_bfloat16 *xh, *xl, *zh, *zl, *hh, *hl, *ffh, *ffl;
    __nv_bfloat16 *wqh, *wql, *woh, *wol, *w1h, *w1l, *w2h, *w2l;
    cudaGetSymbolAddress((void**)&bqkv, g_bqkv);
    cudaGetSymbolAddress((void**)&qkv,  g_qkv);
    cudaGetSymbolAddress((void**)&t1,   g_t1);
    cudaGetSymbolAddress((void**)&hbuf, g_h);
    cudaGetSymbolAddress((void**)&xh,  g_xh);   cudaGetSymbolAddress((void**)&xl,  g_xl);
    cudaGetSymbolAddress((void**)&zh,  g_zh);   cudaGetSymbolAddress((void**)&zl,  g_zl);
    cudaGetSymbolAddress((void**)&hh,  g_hh);   cudaGetSymbolAddress((void**)&hl,  g_hl);
    cudaGetSymbolAddress((void**)&ffh, g_ffh);  cudaGetSymbolAddress((void**)&ffl, g_ffl);
    cudaGetSymbolAddress((void**)&wqh, g_wqkvh); cudaGetSymbolAddress((void**)&wql, g_wqkvl);
    cudaGetSymbolAddress((void**)&woh, g_woh);   cudaGetSymbolAddress((void**)&wol, g_wol);
    cudaGetSymbolAddress((void**)&w1h, g_w1h);   cudaGetSymbolAddress((void**)&w1l, g_w1l);
    cudaGetSymbolAddress((void**)&w2h, g_w2h);   cudaGetSymbolAddress((void**)&w2l, g_w2l);

    cudaFuncSetAttribute(attn_kernel, cudaFuncAttributeMaxDynamicSharedMemorySize,
                         (int)sizeof(AttnSmem));
    cudaFuncSetAttribute(bgemm<false, false, false>, cudaFuncAttributeMaxDynamicSharedMemorySize, GEMM_SMEM);
    cudaFuncSetAttribute(bgemm<false, true,  false>, cudaFuncAttributeMaxDynamicSharedMemorySize, GEMM_SMEM);
    cudaFuncSetAttribute(bgemm<true,  false, true >, cudaFuncAttributeMaxDynamicSharedMemorySize, GEMM_SMEM);

    // operand conversions
    pack_qkv_split<<<(EMB * N3E + 255) / 256, 256>>>(Wq, Wk, Wv, bq, bk, bv);
    split_kernel<<<(EMB * EMB / 4 + 255) / 256, 256>>>(Wo, woh, wol, EMB * EMB / 4);
    split_kernel<<<(EMB * DFF / 4 + 255) / 256, 256>>>(W1, w1h, w1l, EMB * DFF / 4);
    split_kernel<<<(DFF * EMB / 4 + 255) / 256, 256>>>(W2, w2h, w2l, DFF * EMB / 4);
    split_kernel<<<(MR * EMB / 4 + 255) / 256, 256>>>(x, xh, xl, MR * EMB / 4);

    // qkv = x @ Wqkv + b
    bgemm<false, false, false><<<dim3(N3E / 128, MR / 128), 128, GEMM_SMEM>>>(
        xh, xl, wqh, wql, bqkv, nullptr, qkv, nullptr, nullptr, MR, N3E, EMB);

    // attention -> zh/zl
    attn_kernel<<<dim3(LSEQ / 64, HN, BSZ), 256, sizeof(AttnSmem)>>>(qkv, zh, zl);

    // t1 = z @ Wo + bo + x
    bgemm<false, true, false><<<dim3(EMB / 128, MR / 128), 128, GEMM_SMEM>>>(
        zh, zl, woh, wol, bo, x, t1, nullptr, nullptr, MR, EMB, EMB);

    // h = LN1(t1), + hi/lo split
    layernorm_kernel<true><<<MR, 256>>>(t1, g1, be1, hbuf, hh, hl);

    // ff = relu(h @ W1 + c1) -> ffh/ffl
    bgemm<true, false, true><<<dim3(DFF / 128, MR / 128), 128, GEMM_SMEM>>>(
        hh, hl, w1h, w1l, c1, nullptr, nullptr, ffh, ffl, MR, DFF, EMB);

    // t1 = ff @ W2 + c2 + h
    bgemm<false, true, false><<<dim3(EMB / 128, MR / 128), 128, GEMM_SMEM>>>(
        ffh, ffl, w2h, w2l, c2, hbuf, t1, nullptr, nullptr, MR, EMB, DFF);

    // out = LN2(t1)
    layernorm_kernel<false><<<MR, 256>>>(t1, g2, be2, out, nullptr, nullptr);
}

// round 13
// speedup vs baseline: 1.5038x; 1.1402x over previous
#include <cuda_runtime.h>
#include <cuda_bf16.h>
#include <mma.h>
#include <math.h>
#include <stdint.h>

using namespace nvcuda;

#define BSZ  2
#define LSEQ 2048
#define EMB  1024
#define HN   16
#define DHD  64
#define DFF  4096
#define MR   (BSZ*LSEQ)
#define N3E  (3*EMB)

// ---------------------------------------------------------------------------
// Scratch
// ---------------------------------------------------------------------------
__device__ float g_bqkv[N3E];
__device__ float g_q  [(size_t)MR * EMB];
__device__ float g_t1 [(size_t)MR * EMB];
__device__ float g_h  [(size_t)MR * EMB];

__device__ __nv_bfloat16 g_kh [(size_t)MR * EMB], g_kl [(size_t)MR * EMB];
__device__ __nv_bfloat16 g_vh [(size_t)MR * EMB], g_vl [(size_t)MR * EMB];
__device__ __nv_bfloat16 g_xh [(size_t)MR * EMB], g_xl [(size_t)MR * EMB];
__device__ __nv_bfloat16 g_zh [(size_t)MR * EMB], g_zl [(size_t)MR * EMB];
__device__ __nv_bfloat16 g_hh [(size_t)MR * EMB], g_hl [(size_t)MR * EMB];
__device__ __nv_bfloat16 g_ffh[(size_t)MR * DFF], g_ffl[(size_t)MR * DFF];
__device__ __nv_bfloat16 g_wqkvh[(size_t)EMB * N3E], g_wqkvl[(size_t)EMB * N3E];
__device__ __nv_bfloat16 g_woh[(size_t)EMB * EMB],  g_wol[(size_t)EMB * EMB];
__device__ __nv_bfloat16 g_w1h[(size_t)EMB * DFF],  g_w1l[(size_t)EMB * DFF];
__device__ __nv_bfloat16 g_w2h[(size_t)DFF * EMB],  g_w2l[(size_t)DFF * EMB];

// ---------------------------------------------------------------------------
// helpers
// ---------------------------------------------------------------------------
__device__ __forceinline__ uint32_t smem_u32(const void* p) {
    uint32_t a;
    asm("{ .reg .u64 t; cvta.to.shared.u64 t, %1; cvt.u32.u64 %0, t; }" : "=r"(a) : "l"(p));
    return a;
}
#define CP_ASYNC(dst, src) asm volatile("cp.async.cg.shared.global [%0], [%1], 16;" :: "r"(dst), "l"(src))
#define CP_COMMIT()        asm volatile("cp.async.commit_group;" ::: "memory")
#define CP_WAIT(n)         asm volatile("cp.async.wait_group %0;" :: "n"(n) : "memory")

__device__ __forceinline__ void split2(float v, __nv_bfloat16& h, __nv_bfloat16& l) {
    h = __float2bfloat16(v);
    l = __float2bfloat16(v - __bfloat162float(h));
}

// ---------------------------------------------------------------------------
// fp32 -> bf16 hi/lo split (elementwise)
// ---------------------------------------------------------------------------
__global__ void split_kernel(const float* __restrict__ src, __nv_bfloat16* __restrict__ h,
                             __nv_bfloat16* __restrict__ l, int n4)
{
    int i = blockIdx.x * blockDim.x + threadIdx.x;
    if (i >= n4) return;
    float4 v = ((const float4*)src)[i];
    __nv_bfloat162 h01, h23, l01, l23;
    split2(v.x, h01.x, l01.x); split2(v.y, h01.y, l01.y);
    split2(v.z, h23.x, l23.x); split2(v.w, h23.y, l23.y);
    uint2 hv, lv;
    hv.x = *(uint32_t*)&h01; hv.y = *(uint32_t*)&h23;
    lv.x = *(uint32_t*)&l01; lv.y = *(uint32_t*)&l23;
    ((uint2*)h)[i] = hv;
    ((uint2*)l)[i] = lv;
}

__global__ void pack_qkv_split(const float* __restrict__ Wq, const float* __restrict__ Wk,
                               const float* __restrict__ Wv, const float* __restrict__ bq,
                               const float* __restrict__ bk, const float* __restrict__ bv)
{
    int idx = blockIdx.x * blockDim.x + threadIdx.x;
    if (idx < EMB * N3E) {
        int n = idx % N3E, e = idx / N3E;
        int proj = n / EMB, hd = n % EMB;
        const float* W = (proj == 0) ? Wq : (proj == 1) ? Wk : Wv;
        float v = W[(size_t)(hd >> 6) * EMB * DHD + (size_t)e * DHD + (hd & 63)];
        __nv_bfloat16 h, l; split2(v, h, l);
        g_wqkvh[idx] = h; g_wqkvl[idx] = l;
    }
    if (idx < N3E) {
        int proj = idx / EMB, hd = idx % EMB;
        const float* bb = (proj == 0) ? bq : (proj == 1) ? bk : bv;
        g_bqkv[idx] = bb[hd];
    }
}

// ---------------------------------------------------------------------------
// bf16x3 WMMA GEMM, cp.async 3-stage. CTA 128x128, BK=32, 128 thr (2x2 warps).
// MODE: 1 = f32 C = acc+bias+res; 2 = bf16 hi/lo split of relu(acc+bias);
//       3 = qkv: proj0 -> f32 C, proj1 -> Chi/Clo, proj2 -> Ch2/Cl2 (width 1024)
// ---------------------------------------------------------------------------
#define STG       37888
#define GEMM_SMEM (3 * STG)

__device__ __forceinline__ void issue_tile(uint32_t sbase,
    const __nv_bfloat16* __restrict__ Ah, const __nv_bfloat16* __restrict__ Al,
    const __nv_bfloat16* __restrict__ Bh, const __nv_bfloat16* __restrict__ Bl,
    int K, int N, int m0, int n0, int kt, int tid)
{
    const __nv_bfloat16* pah = Ah + (size_t)(m0 + tid) * K + kt;
    const __nv_bfloat16* pal = Al + (size_t)(m0 + tid) * K + kt;
    uint32_t da  = sbase + tid * 80;
    uint32_t dal = sbase + 10240 + tid * 80;
#pragma unroll
    for (int i = 0; i < 4; ++i) CP_ASYNC(da  + i * 16, pah + i * 8);
#pragma unroll
    for (int i = 0; i < 4; ++i) CP_ASYNC(dal + i * 16, pal + i * 8);
    int br = tid >> 2, bc = tid & 3;
    const __nv_bfloat16* pbh = Bh + (size_t)(kt + br) * N + n0 + bc * 8;
    const __nv_bfloat16* pbl = Bl + (size_t)(kt + br) * N + n0 + bc * 8;
    uint32_t db  = sbase + 20480 + br * 272 + bc * 16;
    uint32_t dbl = sbase + 29184 + br * 272 + bc * 16;
#pragma unroll
    for (int i = 0; i < 4; ++i) CP_ASYNC(db  + i * 64, pbh + i * 32);
#pragma unroll
    for (int i = 0; i < 4; ++i) CP_ASYNC(dbl + i * 64, pbl + i * 32);
}

template<int MODE>
__global__ __launch_bounds__(128)
void bgemm(const __nv_bfloat16* __restrict__ Ah, const __nv_bfloat16* __restrict__ Al,
           const __nv_bfloat16* __restrict__ Bh, const __nv_bfloat16* __restrict__ Bl,
           const float* __restrict__ bias, const float* __restrict__ res,
           float* __restrict__ C, __nv_bfloat16* __restrict__ Chi,
           __nv_bfloat16* __restrict__ Clo, __nv_bfloat16* __restrict__ Ch2,
           __nv_bfloat16* __restrict__ Cl2, int M, int N, int K)
{
    extern __shared__ char smem[];
    const uint32_t sb = smem_u32(smem);
    const int tid = threadIdx.x;
    const int wid = tid >> 5;
    const int wm = wid >> 1, wn = wid & 1;
    const int bx = blockIdx.x, by = blockIdx.y;
    const int m0 = by * 128, n0 = bx * 128;
    const int NT = K / 32;

    wmma::fragment<wmma::accumulator, 16, 16, 16, float> acc[4][4];
#pragma unroll
    for (int i = 0; i < 4; ++i)
#pragma unroll
        for (int j = 0; j < 4; ++j) wmma::fill_fragment(acc[i][j], 0.f);

#pragma unroll
    for (int s = 0; s < 3; ++s) {
        issue_tile(sb + s * STG, Ah, Al, Bh, Bl, K, N, m0, n0, s * 32, tid);
        CP_COMMIT();
    }

    for (int t = 0; t < NT; ++t) {
        CP_WAIT(2);
        __syncthreads();

        const int buf = t % 3;
        const __nv_bfloat16* AHs = (const __nv_bfloat16*)(smem + buf * STG);
        const __nv_bfloat16* ALs = (const __nv_bfloat16*)(smem + buf * STG + 10240);
        const __nv_bfloat16* BHs = (const __nv_bfloat16*)(smem + buf * STG + 20480);
        const __nv_bfloat16* BLs = (const __nv_bfloat16*)(smem + buf * STG + 29184);

#pragma unroll
        for (int ks = 0; ks < 2; ++ks) {
            wmma::fragment<wmma::matrix_a, 16, 16, 16, __nv_bfloat16, wmma::row_major> fah[4], fal[4];
#pragma unroll
            for (int i = 0; i < 4; ++i) {
                int off = (wm * 64 + i * 16) * 40 + ks * 16;
                wmma::load_matrix_sync(fah[i], AHs + off, 40);
                wmma::load_matrix_sync(fal[i], ALs + off, 40);
            }
#pragma unroll
            for (int j = 0; j < 4; ++j) {
                wmma::fragment<wmma::matrix_b, 16, 16, 16, __nv_bfloat16, wmma::row_major> fbh, fbl;
                int off = (ks * 16) * 136 + wn * 64 + j * 16;
                wmma::load_matrix_sync(fbh, BHs + off, 136);
                wmma::load_matrix_sync(fbl, BLs + off, 136);
#pragma unroll
                for (int i = 0; i < 4; ++i) {
                    wmma::mma_sync(acc[i][j], fah[i], fbh, acc[i][j]);
                    wmma::mma_sync(acc[i][j], fah[i], fbl, acc[i][j]);
                    wmma::mma_sync(acc[i][j], fal[i], fbh, acc[i][j]);
                }
            }
        }

        __syncthreads();
        if (t + 3 < NT)
            issue_tile(sb + buf * STG, Ah, Al, Bh, Bl, K, N, m0, n0, (t + 3) * 32, tid);
        CP_COMMIT();
    }

    CP_WAIT(0);
    __syncthreads();

    float* Cs = (float*)smem;
    float* wbase = Cs + wid * 4352;
#pragma unroll
    for (int i = 0; i < 4; ++i)
#pragma unroll
        for (int j = 0; j < 4; ++j)
            wmma::store_matrix_sync(wbase + (i * 16) * 68 + j * 16, acc[i][j], 68,
                                    wmma::mem_row_major);
    __syncthreads();

    {
        const int m = m0 + tid;
        const float* bp = bias + n0;
        const float* rp = (MODE == 1) ? (res + (size_t)m * N + n0) : nullptr;
        const int proj = (MODE == 3) ? (n0 >> 10) : 0;
        const int colb = (MODE == 3) ? (n0 & 1023) : 0;
#pragma unroll 8
        for (int cb = 0; cb < 128; cb += 4) {
            int w = ((tid >> 6) << 1) | (cb >> 6);
            const float* sp = Cs + w * 4352 + (tid & 63) * 68 + (cb & 63);
            float4 v = *(const float4*)sp;
            float4 bi = *(const float4*)(bp + cb);
            v.x += bi.x; v.y += bi.y; v.z += bi.z; v.w += bi.w;
            if (MODE == 1) {
                float4 rr = *(const float4*)(rp + cb);
                v.x += rr.x; v.y += rr.y; v.z += rr.z; v.w += rr.w;
            }
            if (MODE == 2) {
                v.x = fmaxf(v.x, 0.f); v.y = fmaxf(v.y, 0.f);
                v.z = fmaxf(v.z, 0.f); v.w = fmaxf(v.w, 0.f);
            }
            if (MODE == 2 || (MODE == 3 && proj != 0)) {
                __nv_bfloat162 h01, h23, l01, l23;
                split2(v.x, h01.x, l01.x); split2(v.y, h01.y, l01.y);
                split2(v.z, h23.x, l23.x); split2(v.w, h23.y, l23.y);
                uint2 hv, lv;
                hv.x = *(uint32_t*)&h01; hv.y = *(uint32_t*)&h23;
                lv.x = *(uint32_t*)&l01; lv.y = *(uint32_t*)&l23;
                if (MODE == 2) {
                    *(uint2*)&Chi[(size_t)m * N + n0 + cb] = hv;
                    *(uint2*)&Clo[(size_t)m * N + n0 + cb] = lv;
                } else {
                    __nv_bfloat16* H = (proj == 1) ? Chi : Ch2;
                    __nv_bfloat16* L = (proj == 1) ? Clo : Cl2;
                    *(uint2*)&H[(size_t)m * 1024 + colb + cb] = hv;
                    *(uint2*)&L[(size_t)m * 1024 + colb + cb] = lv;
                }
            } else if (MODE == 3) {
                *(float4*)&C[(size_t)m * 1024 + colb + cb] = v;
            } else {
                *(float4*)&C[(size_t)m * N + n0 + cb] = v;
            }
        }
    }
}

// ---------------------------------------------------------------------------
// LayerNorm (optional split output)
// ---------------------------------------------------------------------------
__device__ __forceinline__ float block_sum_1024(float v, float* red)
{
#pragma unroll
    for (int o = 16; o; o >>= 1) v += __shfl_xor_sync(0xffffffffu, v, o);
    int w = threadIdx.x >> 5;
    if ((threadIdx.x & 31) == 0) red[w] = v;
    __syncthreads();
    if (threadIdx.x < 32) {
        float t = (threadIdx.x < 8) ? red[threadIdx.x] : 0.f;
#pragma unroll
        for (int o = 4; o; o >>= 1) t += __shfl_xor_sync(0xffffffffu, t, o);
        if (threadIdx.x == 0) red[0] = t;
    }
    __syncthreads();
    float r = red[0];
    __syncthreads();
    return r;
}

template<bool SPLIT>
__global__ __launch_bounds__(256)
void layernorm_kernel(const float* __restrict__ in, const float* __restrict__ g,
                      const float* __restrict__ beta, float* __restrict__ out,
                      __nv_bfloat16* __restrict__ oh, __nv_bfloat16* __restrict__ ol)
{
    __shared__ float red[8];
    const int row = blockIdx.x;
    const int tid = threadIdx.x;
    float4 v = ((const float4*)(in + (size_t)row * EMB))[tid];
    float mean = block_sum_1024(v.x + v.y + v.z + v.w, red) * (1.f / EMB);
    float dx = v.x - mean, dy = v.y - mean, dz = v.z - mean, dw = v.w - mean;
    float var = block_sum_1024(dx * dx + dy * dy + dz * dz + dw * dw, red) * (1.f / EMB);
    float rstd = rsqrtf(var + 1e-5f);
    float4 gv = ((const float4*)g)[tid];
    float4 bv = ((const float4*)beta)[tid];
    float4 o;
    o.x = dx * rstd * gv.x + bv.x;
    o.y = dy * rstd * gv.y + bv.y;
    o.z = dz * rstd * gv.z + bv.z;
    o.w = dw * rstd * gv.w + bv.w;
    ((float4*)(out + (size_t)row * EMB))[tid] = o;
    if (SPLIT) {
        __nv_bfloat162 h01, h23, l01, l23;
        split2(o.x, h01.x, l01.x); split2(o.y, h01.y, l01.y);
        split2(o.z, h23.x, l23.x); split2(o.w, h23.y, l23.y);
        uint2 hv, lv;
        hv.x = *(uint32_t*)&h01; hv.y = *(uint32_t*)&h23;
        lv.x = *(uint32_t*)&l01; lv.y = *(uint32_t*)&l23;
        ((uint2*)(oh + (size_t)row * EMB))[tid] = hv;
        ((uint2*)(ol + (size_t)row * EMB))[tid] = lv;
    }
}

// ---------------------------------------------------------------------------
// WMMA causal flash attention. CTA = (64 queries, head, batch). 256 threads.
// S = Q*K^T via bf16x3 wmma; online softmax (4 threads/row); PV via bf16x3.
// O kept in smem f32, rescaled by alpha each step.
// ---------------------------------------------------------------------------
struct ASmem {
    __nv_bfloat16 Qh[64*72], Ql[64*72], Kh[64*72], Kl[64*72];
    __nv_bfloat16 Vh[64*72], Vl[64*72], Ph[64*72], Pl[64*72];
    float Ss[64*72];
    float Os[64*72];
    float mrow[64], lrow[64], arow[64];
    float pm[4*65], ps[4*65];
};

__global__ __launch_bounds__(256, 2)
void attn_wmma(const float* __restrict__ q,
               const __nv_bfloat16* __restrict__ kh, const __nv_bfloat16* __restrict__ kl,
               const __nv_bfloat16* __restrict__ vh, const __nv_bfloat16* __restrict__ vl,
               __nv_bfloat16* __restrict__ zh, __nv_bfloat16* __restrict__ zl)
{
    extern __shared__ char raw[];
    ASmem& sm = *reinterpret_cast<ASmem*>(raw);

    const int qb = blockIdx.x, h = blockIdx.y, b = blockIdx.z;
    const int tid = threadIdx.x, wid = tid >> 5;
    const int wy = wid >> 1, wx = wid & 1;     // 4x2 warp grid, 16x32 tiles
    const int r = tid >> 2, sg = tid & 3, c0 = sg * 16;

    // load Q (scale + split), zero O
    {
        const float* qp = q + (size_t)(b * LSEQ + qb * 64 + r) * EMB + h * 64 + c0;
#pragma unroll
        for (int i = 0; i < 4; ++i) {
            float4 v = *(const float4*)(qp + i * 4);
            v.x *= 0.125f; v.y *= 0.125f; v.z *= 0.125f; v.w *= 0.125f;
            split2(v.x, sm.Qh[r*72 + c0 + i*4 + 0], sm.Ql[r*72 + c0 + i*4 + 0]);
            split2(v.y, sm.Qh[r*72 + c0 + i*4 + 1], sm.Ql[r*72 + c0 + i*4 + 1]);
            split2(v.z, sm.Qh[r*72 + c0 + i*4 + 2], sm.Ql[r*72 + c0 + i*4 + 2]);
            split2(v.w, sm.Qh[r*72 + c0 + i*4 + 3], sm.Ql[r*72 + c0 + i*4 + 3]);
            *(float4*)&sm.Os[r*72 + c0 + i*4] = make_float4(0.f, 0.f, 0.f, 0.f);
        }
    }
    if (tid < 64) { sm.mrow[tid] = -1e30f; sm.lrow[tid] = 0.f; }

    for (int kb = 0; kb <= qb; ++kb) {
        __syncthreads();
        // load K,V hi/lo tiles (uint4 = 8 bf16)
        {
            size_t go = (size_t)(b * LSEQ + kb * 64 + r) * EMB + h * 64 + c0;
            *(uint4*)&sm.Kh[r*72 + c0]     = *(const uint4*)(kh + go);
            *(uint4*)&sm.Kh[r*72 + c0 + 8] = *(const uint4*)(kh + go + 8);
            *(uint4*)&sm.Kl[r*72 + c0]     = *(const uint4*)(kl + go);
            *(uint4*)&sm.Kl[r*72 + c0 + 8] = *(const uint4*)(kl + go + 8);
            *(uint4*)&sm.Vh[r*72 + c0]     = *(const uint4*)(vh + go);
            *(uint4*)&sm.Vh[r*72 + c0 + 8] = *(const uint4*)(vh + go + 8);
            *(uint4*)&sm.Vl[r*72 + c0]     = *(const uint4*)(vl + go);
            *(uint4*)&sm.Vl[r*72 + c0 + 8] = *(const uint4*)(vl + go + 8);
        }
        __syncthreads();

        // S = Q K^T (bf16x3)
        {
            wmma::fragment<wmma::accumulator, 16, 16, 16, float> s[2];
            wmma::fill_fragment(s[0], 0.f);
            wmma::fill_fragment(s[1], 0.f);
#pragma unroll
            for (int kk = 0; kk < 4; ++kk) {
                wmma::fragment<wmma::matrix_a, 16, 16, 16, __nv_bfloat16, wmma::row_major> fah, fal;
                wmma::load_matrix_sync(fah, &sm.Qh[(wy*16)*72 + kk*16], 72);
                wmma::load_matrix_sync(fal, &sm.Ql[(wy*16)*72 + kk*16], 72);
#pragma unroll
                for (int j = 0; j < 2; ++j) {
                    wmma::fragment<wmma::matrix_b, 16, 16, 16, __nv_bfloat16, wmma::col_major> fbh, fbl;
                    wmma::load_matrix_sync(fbh, &sm.Kh[(wx*32 + j*16)*72 + kk*16], 72);
                    wmma::load_matrix_sync(fbl, &sm.Kl[(wx*32 + j*16)*72 + kk*16], 72);
                    wmma::mma_sync(s[j], fah, fbh, s[j]);
                    wmma::mma_sync(s[j], fah, fbl, s[j]);
                    wmma::mma_sync(s[j], fal, fbh, s[j]);
                }
            }
            wmma::store_matrix_sync(&sm.Ss[(wy*16)*72 + wx*32],      s[0], 72, wmma::mem_row_major);
            wmma::store_matrix_sync(&sm.Ss[(wy*16)*72 + wx*32 + 16], s[1], 72, wmma::mem_row_major);
        }
        __syncthreads();

        // softmax: 4 threads per row
        const bool diag = (kb == qb);
        {
            float mx = -1e30f;
#pragma unroll
            for (int c = 0; c < 16; ++c) {
                float sv = sm.Ss[r*72 + c0 + c];
                if (diag && (c0 + c > r)) sv = -1e30f;
                mx = fmaxf(mx, sv);
            }
            sm.pm[sg*65 + r] = mx;
        }
        __syncthreads();
        if (sg == 0) {
            float mo = sm.mrow[r];
            float mn = fmaxf(fmaxf(sm.pm[r], sm.pm[65 + r]),
                             fmaxf(sm.pm[130 + r], sm.pm[195 + r]));
            mn = fmaxf(mn, mo);
            sm.arow[r] = __expf(mo - mn);
            sm.mrow[r] = mn;
        }
        __syncthreads();
        {
            float mn = sm.mrow[r];
            float psum = 0.f;
#pragma unroll
            for (int c = 0; c < 16; ++c) {
                float sv = sm.Ss[r*72 + c0 + c];
                float p = (diag && (c0 + c > r)) ? 0.f : __expf(sv - mn);
                split2(p, sm.Ph[r*72 + c0 + c], sm.Pl[r*72 + c0 + c]);
                psum += p;
            }
            sm.ps[sg*65 + r] = psum;
        }
        __syncthreads();
        if (sg == 0)
            sm.lrow[r] = sm.lrow[r] * sm.arow[r]
                       + sm.ps[r] + sm.ps[65 + r] + sm.ps[130 + r] + sm.ps[195 + r];

        // PV (bf16x3) -> Ss
        {
            wmma::fragment<wmma::accumulator, 16, 16, 16, float> o[2];
            wmma::fill_fragment(o[0], 0.f);
            wmma::fill_fragment(o[1], 0.f);
#pragma unroll
            for (int kk = 0; kk < 4; ++kk) {
                wmma::fragment<wmma::matrix_a, 16, 16, 16, __nv_bfloat16, wmma::row_major> pah, pal;
                wmma::load_matrix_sync(pah, &sm.Ph[(wy*16)*72 + kk*16], 72);
                wmma::load_matrix_sync(pal, &sm.Pl[(wy*16)*72 + kk*16], 72);
#pragma unroll
                for (int j = 0; j < 2; ++j) {
                    wmma::fragment<wmma::matrix_b, 16, 16, 16, __nv_bfloat16, wmma::row_major> vbh, vbl;
                    wmma::load_matrix_sync(vbh, &sm.Vh[(kk*16)*72 + wx*32 + j*16], 72);
                    wmma::load_matrix_sync(vbl, &sm.Vl[(kk*16)*72 + wx*32 + j*16], 72);
                    wmma::mma_sync(o[j], pah, vbh, o[j]);
                    wmma::mma_sync(o[j], pah, vbl, o[j]);
                    wmma::mma_sync(o[j], pal, vbh, o[j]);
                }
            }
            wmma::store_matrix_sync(&sm.Ss[(wy*16)*72 + wx*32],      o[0], 72, wmma::mem_row_major);
            wmma::store_matrix_sync(&sm.Ss[(wy*16)*72 + wx*32 + 16], o[1], 72, wmma::mem_row_major);
        }
        __syncthreads();

        // O = O*alpha + PV
        {
            float al = sm.arow[r];
#pragma unroll
            for (int i = 0; i < 4; ++i) {
                float4 ov = *(float4*)&sm.Os[r*72 + c0 + i*4];
                float4 pv = *(const float4*)&sm.Ss[r*72 + c0 + i*4];
                ov.x = ov.x * al + pv.x; ov.y = ov.y * al + pv.y;
                ov.z = ov.z * al + pv.z; ov.w = ov.w * al + pv.w;
                *(float4*)&sm.Os[r*72 + c0 + i*4] = ov;
            }
        }
    }
    __syncthreads();

    // final: normalize, split, store
    {
        float inv = 1.f / sm.lrow[r];
        uint32_t hp[8], lp[8];
#pragma unroll
        for (int cc = 0; cc < 8; ++cc) {
            float v0 = sm.Os[r*72 + c0 + cc*2]     * inv;
            float v1 = sm.Os[r*72 + c0 + cc*2 + 1] * inv;
            __nv_bfloat162 h2, l2;
            split2(v0, h2.x, l2.x);
            split2(v1, h2.y, l2.y);
            hp[cc] = *(uint32_t*)&h2;
            lp[cc] = *(uint32_t*)&l2;
        }
        size_t off = (size_t)(b * LSEQ + qb * 64 + r) * EMB + h * 64 + c0;
        *(uint4*)&zh[off]     = make_uint4(hp[0], hp[1], hp[2], hp[3]);
        *(uint4*)&zh[off + 8] = make_uint4(hp[4], hp[5], hp[6], hp[7]);
        *(uint4*)&zl[off]     = make_uint4(lp[0], lp[1], lp[2], lp[3]);
        *(uint4*)&zl[off + 8] = make_uint4(lp[4], lp[5], lp[6], lp[7]);
    }
}

// ---------------------------------------------------------------------------
// Launch
// ---------------------------------------------------------------------------
extern "C" void kernel_launch(void* const* d_in, const int* in_sizes, int n_in,
                              void* d_out, int out_size)
{
    const float* x   = (const float*)d_in[0];
    const float* Wq  = (const float*)d_in[2];
    const float* bq  = (const float*)d_in[3];
    const float* Wk  = (const float*)d_in[4];
    const float* bk  = (const float*)d_in[5];
    const float* Wv  = (const float*)d_in[6];
    const float* bv  = (const float*)d_in[7];
    const float* Wo  = (const float*)d_in[8];
    const float* bo  = (const float*)d_in[9];
    const float* W1  = (const float*)d_in[10];
    const float* c1  = (const float*)d_in[11];
    const float* W2  = (const float*)d_in[12];
    const float* c2  = (const float*)d_in[13];
    const float* g1  = (const float*)d_in[14];
    const float* be1 = (const float*)d_in[15];
    const float* g2  = (const float*)d_in[16];
    const float* be2 = (const float*)d_in[17];
    float* out = (float*)d_out;

    float *bqkv, *qbuf, *t1, *hbuf;
    __nv_bfloat16 *kh, *kl, *vh, *vl, *xh, *xl, *zh, *zl, *hh, *hl, *ffh, *ffl;
    __nv_bfloat16 *wqh, *wql, *woh, *wol, *w1h, *w1l, *w2h, *w2l;
    cudaGetSymbolAddress((void**)&bqkv, g_bqkv);
    cudaGetSymbolAddress((void**)&qbuf, g_q);
    cudaGetSymbolAddress((void**)&t1,   g_t1);
    cudaGetSymbolAddress((void**)&hbuf, g_h);
    cudaGetSymbolAddress((void**)&kh, g_kh); cudaGetSymbolAddress((void**)&kl, g_kl);
    cudaGetSymbolAddress((void**)&vh, g_vh); cudaGetSymbolAddress((void**)&vl, g_vl);
    cudaGetSymbolAddress((void**)&xh, g_xh); cudaGetSymbolAddress((void**)&xl, g_xl);
    cudaGetSymbolAddress((void**)&zh, g_zh); cudaGetSymbolAddress((void**)&zl, g_zl);
    cudaGetSymbolAddress((void**)&hh, g_hh); cudaGetSymbolAddress((void**)&hl, g_hl);
    cudaGetSymbolAddress((void**)&ffh, g_ffh); cudaGetSymbolAddress((void**)&ffl, g_ffl);
    cudaGetSymbolAddress((void**)&wqh, g_wqkvh); cudaGetSymbolAddress((void**)&wql, g_wqkvl);
    cudaGetSymbolAddress((void**)&woh, g_woh);   cudaGetSymbolAddress((void**)&wol, g_wol);
    cudaGetSymbolAddress((void**)&w1h, g_w1h);   cudaGetSymbolAddress((void**)&w1l, g_w1l);
    cudaGetSymbolAddress((void**)&w2h, g_w2h);   cudaGetSymbolAddress((void**)&w2l, g_w2l);

    cudaFuncSetAttribute(attn_wmma, cudaFuncAttributeMaxDynamicSharedMemorySize,
                         (int)sizeof(ASmem));
    cudaFuncSetAttribute(bgemm<1>, cudaFuncAttributeMaxDynamicSharedMemorySize, GEMM_SMEM);
    cudaFuncSetAttribute(bgemm<2>, cudaFuncAttributeMaxDynamicSharedMemorySize, GEMM_SMEM);
    cudaFuncSetAttribute(bgemm<3>, cudaFuncAttributeMaxDynamicSharedMemorySize, GEMM_SMEM);

    // conversions
    pack_qkv_split<<<(EMB * N3E + 255) / 256, 256>>>(Wq, Wk, Wv, bq, bk, bv);
    split_kernel<<<(EMB * EMB / 4 + 255) / 256, 256>>>(Wo, woh, wol, EMB * EMB / 4);
    split_kernel<<<(EMB * DFF / 4 + 255) / 256, 256>>>(W1, w1h, w1l, EMB * DFF / 4);
    split_kernel<<<(DFF * EMB / 4 + 255) / 256, 256>>>(W2, w2h, w2l, DFF * EMB / 4);
    split_kernel<<<(MR * EMB / 4 + 255) / 256, 256>>>(x, xh, xl, MR * EMB / 4);

    // qkv: q -> f32, k/v -> bf16 hi/lo splits
    bgemm<3><<<dim3(N3E / 128, MR / 128), 128, GEMM_SMEM>>>(
        xh, xl, wqh, wql, bqkv, nullptr, qbuf, kh, kl, vh, vl, MR, N3E, EMB);

    // attention -> zh/zl
    attn_wmma<<<dim3(LSEQ / 64, HN, BSZ), 256, sizeof(ASmem)>>>(
        qbuf, kh, kl, vh, vl, zh, zl);

    // t1 = z @ Wo + bo + x
    bgemm<1><<<dim3(EMB / 128, MR / 128), 128, GEMM_SMEM>>>(
        zh, zl, woh, wol, bo, x, t1, nullptr, nullptr, nullptr, nullptr, MR, EMB, EMB);

    // h = LN1(t1) + split
    layernorm_kernel<true><<<MR, 256>>>(t1, g1, be1, hbuf, hh, hl);

    // ff = relu(h @ W1 + c1) -> ffh/ffl
    bgemm<2><<<dim3(DFF / 128, MR / 128), 128, GEMM_SMEM>>>(
        hh, hl, w1h, w1l, c1, nullptr, nullptr, ffh, ffl, nullptr, nullptr, MR, DFF, EMB);

    // t1 = ff @ W2 + c2 + h
    bgemm<1><<<dim3(EMB / 128, MR / 128), 128, GEMM_SMEM>>>(
        ffh, ffl, w2h, w2l, c2, hbuf, t1, nullptr, nullptr, nullptr, nullptr, MR, EMB, DFF);

    // out = LN2(t1)
    layernorm_kernel<false><<<MR, 256>>>(t1, g2, be2, out, nullptr, nullptr);
}